// round 2
// baseline (speedup 1.0000x reference)
#include <cuda_runtime.h>
#include <cuda_bf16.h>
#include <math.h>

// Problem constants
#define Bc 4
#define Tc 2048
#define Cc 1024
#define Hc 16
#define HDc 64
#define Mc (Bc * Tc)   // 8192
#define N3c (3 * Cc)   // 3072

// ---------------------------------------------------------------------------
// Scratch (static device globals; no runtime allocation allowed)
// ---------------------------------------------------------------------------
__device__ float g_qkv[(size_t)Mc * N3c];          // [B*T, 3C]
__device__ float g_q[(size_t)Bc * Hc * Tc * HDc];  // [B,H,T,HD]
__device__ float g_k[(size_t)Bc * Hc * Tc * HDc];
__device__ float g_v[(size_t)Bc * Hc * Tc * HDc];
__device__ float g_att[(size_t)Mc * Cc];           // [B,T,C]
__device__ float g_invfreq[HDc / 2];

// ---------------------------------------------------------------------------
// inv_freq in double (tiny, once per launch) — matches 1/10000^(l/32)
// ---------------------------------------------------------------------------
__global__ void compute_inv_kernel() {
    int l = threadIdx.x;
    if (l < HDc / 2) {
        double e = (double)(2 * l) / (double)HDc;
        g_invfreq[l] = (float)(1.0 / pow(10000.0, e));
    }
}

// ---------------------------------------------------------------------------
// Accurate fp32 sin/cos (Cody-Waite + cephes minimax). Immune to fast-math.
// Valid for 0 <= x < ~1e4 (freq <= 2047 here). ~1e-7 abs error.
// ---------------------------------------------------------------------------
__device__ __forceinline__ void sincos_ref(float x, float& s_out, float& c_out) {
    float n = rintf(x * 0.63661977236758134f);  // x * 2/pi
    int qn = (int)n;
    float r = fmaf(-n, 1.5707962512969971e+00f, x);
    r = fmaf(-n, 7.5497894158615964e-08f, r);
    r = fmaf(-n, 5.3903025299577648e-15f, r);
    float x2 = r * r;
    float sp = fmaf(x2, fmaf(x2, -1.9515295891e-4f, 8.3321608736e-3f), -1.6666654611e-1f);
    float sr = fmaf(r * x2, sp, r);
    float cr = fmaf(x2,
                    fmaf(x2,
                         fmaf(x2, fmaf(x2, 2.443315711809948e-5f, -1.388731625493765e-3f),
                              4.166664568298827e-2f),
                         -0.5f),
                    1.0f);
    float ss, cc;
    switch (qn & 3) {
        case 0:  ss = sr;  cc = cr;  break;
        case 1:  ss = cr;  cc = -sr; break;
        case 2:  ss = -sr; cc = -cr; break;
        default: ss = -cr; cc = sr;  break;
    }
    s_out = ss;
    c_out = cc;
}

// ---------------------------------------------------------------------------
// SGEMM (NT): C[m,n] = sum_k A[m,k] * B[n,k].  M,N % 128 == 0, K % 8 == 0.
// 128x128x8 tile, 256 threads, 8x8 per thread (split 4+4 tiles).
// ---------------------------------------------------------------------------
__global__ void __launch_bounds__(256) gemm_nt_128(
    const float* __restrict__ A, const float* __restrict__ Bm,
    float* __restrict__ Cm, int M, int N, int K) {
    __shared__ float As[8][128];
    __shared__ float Bs[8][128];
    const int tid = threadIdx.x;
    const int m0 = blockIdx.y * 128;
    const int n0 = blockIdx.x * 128;
    const int lr = tid >> 1;          // 0..127
    const int lc = (tid & 1) << 2;    // 0 or 4
    const int tx = tid & 15;
    const int ty = tid >> 4;

    float acc[8][8];
#pragma unroll
    for (int i = 0; i < 8; i++)
#pragma unroll
        for (int j = 0; j < 8; j++) acc[i][j] = 0.f;

    const float* Ap = A + (size_t)(m0 + lr) * K + lc;
    const float* Bp = Bm + (size_t)(n0 + lr) * K + lc;

    for (int k0 = 0; k0 < K; k0 += 8) {
        float4 av = *(const float4*)(Ap + k0);
        float4 bv = *(const float4*)(Bp + k0);
        As[lc + 0][lr] = av.x; As[lc + 1][lr] = av.y;
        As[lc + 2][lr] = av.z; As[lc + 3][lr] = av.w;
        Bs[lc + 0][lr] = bv.x; Bs[lc + 1][lr] = bv.y;
        Bs[lc + 2][lr] = bv.z; Bs[lc + 3][lr] = bv.w;
        __syncthreads();
#pragma unroll
        for (int k = 0; k < 8; k++) {
            float a[8], b[8];
            *(float4*)&a[0] = *(const float4*)&As[k][ty * 4];
            *(float4*)&a[4] = *(const float4*)&As[k][64 + ty * 4];
            *(float4*)&b[0] = *(const float4*)&Bs[k][tx * 4];
            *(float4*)&b[4] = *(const float4*)&Bs[k][64 + tx * 4];
#pragma unroll
            for (int i = 0; i < 8; i++)
#pragma unroll
                for (int j = 0; j < 8; j++) acc[i][j] = fmaf(a[i], b[j], acc[i][j]);
        }
        __syncthreads();
    }

#pragma unroll
    for (int i = 0; i < 8; i++) {
        int r = m0 + ((i < 4) ? (ty * 4 + i) : (64 + ty * 4 + (i - 4)));
        float4 v0 = make_float4(acc[i][0], acc[i][1], acc[i][2], acc[i][3]);
        float4 v1 = make_float4(acc[i][4], acc[i][5], acc[i][6], acc[i][7]);
        *(float4*)&Cm[(size_t)r * N + n0 + tx * 4] = v0;
        *(float4*)&Cm[(size_t)r * N + n0 + 64 + tx * 4] = v1;
    }
}

// ---------------------------------------------------------------------------
// Fused per-head RMSNorm + RoPE + QKV scatter into [B,H,T,HD].
// One block per (b,t); warp w = head w; lane holds dims (lane, lane+32).
// ---------------------------------------------------------------------------
__global__ void __launch_bounds__(512) norm_rope_kernel(const float* __restrict__ qkv) {
    const int bt = blockIdx.x;
    const int t = bt & (Tc - 1);
    const int b = bt >> 11;  // T = 2048
    const int w = threadIdx.x >> 5;
    const int lane = threadIdx.x & 31;

    const float* base = qkv + (size_t)bt * N3c + w * HDc;
    float q1 = base[lane], q2 = base[lane + 32];
    float k1 = base[Cc + lane], k2 = base[Cc + lane + 32];
    float v1 = base[2 * Cc + lane], v2 = base[2 * Cc + lane + 32];

    float sq = q1 * q1 + q2 * q2;
    float sk = k1 * k1 + k2 * k2;
#pragma unroll
    for (int o = 16; o; o >>= 1) {
        sq += __shfl_xor_sync(0xffffffffu, sq, o);
        sk += __shfl_xor_sync(0xffffffffu, sk, o);
    }
    const float eps = 1.1920928955078125e-07f;
    float rq = rsqrtf(sq * (1.f / 64.f) + eps);
    float rk = rsqrtf(sk * (1.f / 64.f) + eps);
    q1 *= rq; q2 *= rq;
    k1 *= rk; k2 *= rk;

    float freq = (float)t * g_invfreq[lane];
    float sn, cs;
    sincos_ref(freq, sn, cs);
    cs = __bfloat162float(__float2bfloat16(cs));
    sn = __bfloat162float(__float2bfloat16(sn));

    float qy1 = q1 * cs + q2 * sn;
    float qy2 = -q1 * sn + q2 * cs;
    float ky1 = k1 * cs + k2 * sn;
    float ky2 = -k1 * sn + k2 * cs;

    size_t obase = ((size_t)(b * Hc + w) * Tc + t) * HDc;
    g_q[obase + lane] = qy1;       g_q[obase + lane + 32] = qy2;
    g_k[obase + lane] = ky1;       g_k[obase + lane + 32] = ky2;
    g_v[obase + lane] = v1;        g_v[obase + lane + 32] = v2;
}

// ---------------------------------------------------------------------------
// Causal flash attention. 64x64 tiles, HD=64, 256 threads, 4x4 per thread.
// QsT[d][m], KsT[d][n] transposed smem; P tile aliases KsT. 48KB static smem.
// ---------------------------------------------------------------------------
#define FMA16(S, A, Bv)                                                     \
    S[0][0] = fmaf(A.x, Bv.x, S[0][0]); S[0][1] = fmaf(A.x, Bv.y, S[0][1]); \
    S[0][2] = fmaf(A.x, Bv.z, S[0][2]); S[0][3] = fmaf(A.x, Bv.w, S[0][3]); \
    S[1][0] = fmaf(A.y, Bv.x, S[1][0]); S[1][1] = fmaf(A.y, Bv.y, S[1][1]); \
    S[1][2] = fmaf(A.y, Bv.z, S[1][2]); S[1][3] = fmaf(A.y, Bv.w, S[1][3]); \
    S[2][0] = fmaf(A.z, Bv.x, S[2][0]); S[2][1] = fmaf(A.z, Bv.y, S[2][1]); \
    S[2][2] = fmaf(A.z, Bv.z, S[2][2]); S[2][3] = fmaf(A.z, Bv.w, S[2][3]); \
    S[3][0] = fmaf(A.w, Bv.x, S[3][0]); S[3][1] = fmaf(A.w, Bv.y, S[3][1]); \
    S[3][2] = fmaf(A.w, Bv.z, S[3][2]); S[3][3] = fmaf(A.w, Bv.w, S[3][3]);

__global__ void __launch_bounds__(256) attn_kernel() {
    __shared__ float QsT[64 * 64];  // [d][m]
    __shared__ float KsT[64 * 64];  // [d][n]; reused as PsT[n][m]
    __shared__ float Vs[64 * 64];   // [n][d]

    const int qi = blockIdx.x;   // q tile, 0..31
    const int bh = blockIdx.y;   // b*H + h, 0..63
    const int tid = threadIdx.x;
    const int cg = tid & 15, rg = tid >> 4;
    const int c0 = cg * 4, r0 = rg * 4;
    const size_t base = (size_t)bh * Tc * HDc;
    const int qbase = qi * 64;

    const float* Q = g_q + base;
    const float* K = g_k + base;
    const float* V = g_v + base;

    // Load Q tile, transposed & pre-scaled by 1/sqrt(HD) (exact: power of 2)
#pragma unroll
    for (int i = 0; i < 4; i++) {
        int e = tid + i * 256;
        int row = e >> 4;
        int col = (e & 15) << 2;
        float4 v = *(const float4*)&Q[(size_t)(qbase + row) * 64 + col];
        QsT[(col + 0) * 64 + row] = v.x * 0.125f;
        QsT[(col + 1) * 64 + row] = v.y * 0.125f;
        QsT[(col + 2) * 64 + row] = v.z * 0.125f;
        QsT[(col + 3) * 64 + row] = v.w * 0.125f;
    }

    float o[4][4];
    float mrow[4], lrow[4];
#pragma unroll
    for (int i = 0; i < 4; i++) {
        mrow[i] = -1e30f;
        lrow[i] = 0.f;
#pragma unroll
        for (int j = 0; j < 4; j++) o[i][j] = 0.f;
    }

    for (int kt = 0; kt <= qi; kt++) {
        const int kbase = kt * 64;
        __syncthreads();  // prior PV reads done (also covers first-iter Q stores)
#pragma unroll
        for (int i = 0; i < 4; i++) {
            int e = tid + i * 256;
            int row = e >> 4;
            int col = (e & 15) << 2;
            float4 kv = *(const float4*)&K[(size_t)(kbase + row) * 64 + col];
            KsT[(col + 0) * 64 + row] = kv.x;
            KsT[(col + 1) * 64 + row] = kv.y;
            KsT[(col + 2) * 64 + row] = kv.z;
            KsT[(col + 3) * 64 + row] = kv.w;
            *(float4*)&Vs[row * 64 + col] =
                *(const float4*)&V[(size_t)(kbase + row) * 64 + col];
        }
        __syncthreads();

        // S = (Q*scale) @ K^T for this thread's 4x4 patch
        float s[4][4];
#pragma unroll
        for (int i = 0; i < 4; i++)
#pragma unroll
            for (int j = 0; j < 4; j++) s[i][j] = 0.f;
#pragma unroll 16
        for (int d = 0; d < 64; d++) {
            float4 a = *(const float4*)&QsT[d * 64 + r0];
            float4 b = *(const float4*)&KsT[d * 64 + c0];
            FMA16(s, a, b)
        }

        if (kt == qi) {  // diagonal tile: causal mask (kbase == qbase)
#pragma unroll
            for (int i = 0; i < 4; i++)
#pragma unroll
                for (int j = 0; j < 4; j++)
                    if (c0 + j > r0 + i) s[i][j] = -1e30f;
        }

        // Online softmax (row stats across 16 lanes of the row group)
#pragma unroll
        for (int i = 0; i < 4; i++) {
            float mx = fmaxf(fmaxf(s[i][0], s[i][1]), fmaxf(s[i][2], s[i][3]));
#pragma unroll
            for (int off = 1; off < 16; off <<= 1)
                mx = fmaxf(mx, __shfl_xor_sync(0xffffffffu, mx, off));
            float mnew = fmaxf(mx, mrow[i]);
            float corr = __expf(mrow[i] - mnew);
            mrow[i] = mnew;
            float r = 0.f;
#pragma unroll
            for (int j = 0; j < 4; j++) {
                s[i][j] = __expf(s[i][j] - mnew);
                r += s[i][j];
            }
#pragma unroll
            for (int off = 1; off < 16; off <<= 1)
                r += __shfl_xor_sync(0xffffffffu, r, off);
            lrow[i] = lrow[i] * corr + r;
#pragma unroll
            for (int j = 0; j < 4; j++) o[i][j] *= corr;
        }

        __syncthreads();  // everyone done reading KsT
        float* PsT = KsT; // alias
#pragma unroll
        for (int j = 0; j < 4; j++) {
            float4 pv = make_float4(s[0][j], s[1][j], s[2][j], s[3][j]);
            *(float4*)&PsT[(c0 + j) * 64 + r0] = pv;
        }
        __syncthreads();

        // O += P @ V
#pragma unroll 16
        for (int n = 0; n < 64; n++) {
            float4 a = *(const float4*)&PsT[n * 64 + r0];
            float4 b = *(const float4*)&Vs[n * 64 + c0];
            FMA16(o, a, b)
        }
    }

    const int b = bh >> 4, h = bh & 15;
#pragma unroll
    for (int i = 0; i < 4; i++) {
        float inv = 1.f / lrow[i];
        int t = qbase + r0 + i;
        float4 v = make_float4(o[i][0] * inv, o[i][1] * inv,
                               o[i][2] * inv, o[i][3] * inv);
        *(float4*)&g_att[((size_t)(b * Tc + t)) * Cc + h * HDc + c0] = v;
    }
}

// ---------------------------------------------------------------------------
// Launch
// ---------------------------------------------------------------------------
extern "C" void kernel_launch(void* const* d_in, const int* in_sizes, int n_in,
                              void* d_out, int out_size) {
    const float* x = (const float*)d_in[0];       // [B*T, C]
    const float* w_attn = (const float*)d_in[1];  // [3C, C]
    const float* w_proj = (const float*)d_in[2];  // [C, C]
    float* out = (float*)d_out;                   // [B*T, C]

    float* qkv_p = nullptr;
    float* att_p = nullptr;
    cudaGetSymbolAddress((void**)&qkv_p, g_qkv);
    cudaGetSymbolAddress((void**)&att_p, g_att);

    compute_inv_kernel<<<1, 32>>>();

    {
        dim3 grid(N3c / 128, Mc / 128);
        gemm_nt_128<<<grid, 256>>>(x, w_attn, qkv_p, Mc, N3c, Cc);
    }

    norm_rope_kernel<<<Mc, 512>>>(qkv_p);

    {
        dim3 grid(Tc / 64, Bc * Hc);
        attn_kernel<<<grid, 256>>>();
    }

    {
        dim3 grid(Cc / 128, Mc / 128);
        gemm_nt_128<<<grid, 256>>>(att_p, w_proj, out, Mc, Cc, Cc);
    }
}

// round 4
// speedup vs baseline: 1.4087x; 1.4087x over previous
#include <cuda_runtime.h>
#include <cuda_bf16.h>
#include <math.h>
#include <stdint.h>

// Problem constants
#define Bc 4
#define Tc 2048
#define Cc 1024
#define Hc 16
#define HDc 64
#define Mc (Bc * Tc)   // 8192
#define N3c (3 * Cc)   // 3072

// ---------------------------------------------------------------------------
// Scratch (static device globals; no runtime allocation allowed)
// ---------------------------------------------------------------------------
__device__ float g_qkv[(size_t)Mc * N3c];          // [B*T, 3C]
__device__ float g_q[(size_t)Bc * Hc * Tc * HDc];  // [B,H,T,HD]
__device__ float g_k[(size_t)Bc * Hc * Tc * HDc];
__device__ float g_v[(size_t)Bc * Hc * Tc * HDc];
__device__ float g_att[(size_t)Mc * Cc];           // [B,T,C]
__device__ float g_invfreq[HDc / 2];

// hi/lo bf16 splits for tensor-core GEMMs
__device__ __nv_bfloat16 g_xhi[(size_t)Mc * Cc];
__device__ __nv_bfloat16 g_xlo[(size_t)Mc * Cc];
__device__ __nv_bfloat16 g_wahi[(size_t)N3c * Cc];
__device__ __nv_bfloat16 g_walo[(size_t)N3c * Cc];
__device__ __nv_bfloat16 g_wphi[(size_t)Cc * Cc];
__device__ __nv_bfloat16 g_wplo[(size_t)Cc * Cc];
__device__ __nv_bfloat16 g_athi[(size_t)Mc * Cc];
__device__ __nv_bfloat16 g_atlo[(size_t)Mc * Cc];

// ---------------------------------------------------------------------------
// inv_freq in double — matches 1/10000^(l/32)
// ---------------------------------------------------------------------------
__global__ void compute_inv_kernel() {
    int l = threadIdx.x;
    if (l < HDc / 2) {
        double e = (double)(2 * l) / (double)HDc;
        g_invfreq[l] = (float)(1.0 / pow(10000.0, e));
    }
}

// ---------------------------------------------------------------------------
// fp32 -> bf16 hi/lo split (vectorized by 4)
// ---------------------------------------------------------------------------
__global__ void __launch_bounds__(256) split_kernel(
    const float* __restrict__ src, __nv_bfloat16* __restrict__ hi,
    __nv_bfloat16* __restrict__ lo, int n4) {
    int i = blockIdx.x * 256 + threadIdx.x;
    if (i >= n4) return;
    float4 v = ((const float4*)src)[i];
    float f[4] = {v.x, v.y, v.z, v.w};
    __nv_bfloat16 h[4], l[4];
#pragma unroll
    for (int j = 0; j < 4; j++) {
        h[j] = __float2bfloat16_rn(f[j]);
        l[j] = __float2bfloat16_rn(f[j] - __bfloat162float(h[j]));
    }
    ((uint2*)hi)[i] = *(uint2*)h;
    ((uint2*)lo)[i] = *(uint2*)l;
}

// ---------------------------------------------------------------------------
// mma.sync helpers
// ---------------------------------------------------------------------------
__device__ __forceinline__ void ldmx4(uint32_t* r, uint32_t addr) {
    asm volatile(
        "ldmatrix.sync.aligned.m8n8.x4.shared.b16 {%0,%1,%2,%3}, [%4];"
        : "=r"(r[0]), "=r"(r[1]), "=r"(r[2]), "=r"(r[3])
        : "r"(addr));
}

__device__ __forceinline__ void mma_bf16(
    float* d, const uint32_t* a, uint32_t b0, uint32_t b1) {
    asm volatile(
        "mma.sync.aligned.m16n8k16.row.col.f32.bf16.bf16.f32 "
        "{%0,%1,%2,%3}, {%4,%5,%6,%7}, {%8,%9}, {%0,%1,%2,%3};"
        : "+f"(d[0]), "+f"(d[1]), "+f"(d[2]), "+f"(d[3])
        : "r"(a[0]), "r"(a[1]), "r"(a[2]), "r"(a[3]), "r"(b0), "r"(b1));
}

// ---------------------------------------------------------------------------
// HMMA GEMM (NT): C[m,n] = sum_k A[m,k]*B[n,k], bf16 hi/lo split (3 MMAs).
// 128x128 CTA tile, 8 warps (2x4), K-chunks of 32, 40-elem row pitch smem.
// ---------------------------------------------------------------------------
#define PITCH 40  // bf16 elements per smem row (80 bytes, conflict-free ldmatrix)

__global__ void __launch_bounds__(256) gemm_mma(
    const __nv_bfloat16* __restrict__ Ahi, const __nv_bfloat16* __restrict__ Alo,
    const __nv_bfloat16* __restrict__ Bhi, const __nv_bfloat16* __restrict__ Blo,
    float* __restrict__ Cm, int N, int K) {
    __shared__ __align__(16) __nv_bfloat16 sAhi[128 * PITCH];
    __shared__ __align__(16) __nv_bfloat16 sAlo[128 * PITCH];
    __shared__ __align__(16) __nv_bfloat16 sBhi[128 * PITCH];
    __shared__ __align__(16) __nv_bfloat16 sBlo[128 * PITCH];

    const int tid = threadIdx.x;
    const int wid = tid >> 5;
    const int lane = tid & 31;
    const int m0 = blockIdx.y * 128;
    const int n0 = blockIdx.x * 128;
    const int wm = wid >> 2;   // 0..1 -> 64 rows each
    const int wn = wid & 3;    // 0..3 -> 32 cols each

    const uint32_t sa_hi = (uint32_t)__cvta_generic_to_shared(sAhi);
    const uint32_t sa_lo = (uint32_t)__cvta_generic_to_shared(sAlo);
    const uint32_t sb_hi = (uint32_t)__cvta_generic_to_shared(sBhi);
    const uint32_t sb_lo = (uint32_t)__cvta_generic_to_shared(sBlo);

    float acc[4][4][4];
#pragma unroll
    for (int i = 0; i < 4; i++)
#pragma unroll
        for (int j = 0; j < 4; j++)
#pragma unroll
            for (int q = 0; q < 4; q++) acc[i][j][q] = 0.f;

    // ldmatrix lane addressing (within a 16x16 / 16-row x4 footprint)
    const int lrow = lane & 15;
    const int lcolb = (lane >> 4) * 16;  // byte offset 0 or 16 (8 bf16)

    const int nchunk = K >> 5;
    for (int c = 0; c < nchunk; c++) {
        const int k0 = c << 5;
        // Load 4 tiles of [128 rows x 32 bf16] with uint4 (8 bf16) each
#pragma unroll
        for (int i = 0; i < 2; i++) {
            int v = tid + i * 256;
            int row = v >> 2;
            int cq = (v & 3) * 8;
            size_t ga = (size_t)(m0 + row) * K + k0 + cq;
            size_t gb = (size_t)(n0 + row) * K + k0 + cq;
            int so = row * PITCH + cq;
            *(uint4*)(sAhi + so) = *(const uint4*)(Ahi + ga);
            *(uint4*)(sAlo + so) = *(const uint4*)(Alo + ga);
            *(uint4*)(sBhi + so) = *(const uint4*)(Bhi + gb);
            *(uint4*)(sBlo + so) = *(const uint4*)(Blo + gb);
        }
        __syncthreads();

#pragma unroll
        for (int ks = 0; ks < 2; ks++) {
            const uint32_t abase =
                (uint32_t)(((wm * 64 + lrow) * PITCH + ks * 16) * 2) + lcolb;
            const uint32_t bbase =
                (uint32_t)(((wn * 32 + lrow) * PITCH + ks * 16) * 2) + lcolb;

            uint32_t ahi[4][4], alo[4][4];
#pragma unroll
            for (int ti = 0; ti < 4; ti++) {
                uint32_t off = abase + (uint32_t)(ti * 16 * PITCH * 2);
                ldmx4(ahi[ti], sa_hi + off);
                ldmx4(alo[ti], sa_lo + off);
            }
            uint32_t bhi[2][4], blo[2][4];
#pragma unroll
            for (int tg = 0; tg < 2; tg++) {
                uint32_t off = bbase + (uint32_t)(tg * 16 * PITCH * 2);
                ldmx4(bhi[tg], sb_hi + off);
                ldmx4(blo[tg], sb_lo + off);
            }

#pragma unroll
            for (int ti = 0; ti < 4; ti++)
#pragma unroll
                for (int tj = 0; tj < 4; tj++) {
                    const int tg = tj >> 1, sub = tj & 1;
                    // x4 ordering: matrix sub (rows sub*8..) pairs (r[sub], r[sub+2])
                    mma_bf16(acc[ti][tj], ahi[ti], bhi[tg][sub], bhi[tg][sub + 2]);
                    mma_bf16(acc[ti][tj], ahi[ti], blo[tg][sub], blo[tg][sub + 2]);
                    mma_bf16(acc[ti][tj], alo[ti], bhi[tg][sub], bhi[tg][sub + 2]);
                }
        }
        __syncthreads();
    }

    // Epilogue: fp32 stores, float2 per (row, colpair)
    const int g = lane >> 2;
    const int cq = (lane & 3) * 2;
#pragma unroll
    for (int ti = 0; ti < 4; ti++) {
#pragma unroll
        for (int tj = 0; tj < 4; tj++) {
            int row = m0 + wm * 64 + ti * 16 + g;
            int col = n0 + wn * 32 + tj * 8 + cq;
            *(float2*)&Cm[(size_t)row * N + col] =
                make_float2(acc[ti][tj][0], acc[ti][tj][1]);
            *(float2*)&Cm[(size_t)(row + 8) * N + col] =
                make_float2(acc[ti][tj][2], acc[ti][tj][3]);
        }
    }
}

// ---------------------------------------------------------------------------
// Accurate fp32 sin/cos (Cody-Waite + cephes minimax). Immune to fast-math.
// ---------------------------------------------------------------------------
__device__ __forceinline__ void sincos_ref(float x, float& s_out, float& c_out) {
    float n = rintf(x * 0.63661977236758134f);
    int qn = (int)n;
    float r = fmaf(-n, 1.5707962512969971e+00f, x);
    r = fmaf(-n, 7.5497894158615964e-08f, r);
    r = fmaf(-n, 5.3903025299577648e-15f, r);
    float x2 = r * r;
    float sp = fmaf(x2, fmaf(x2, -1.9515295891e-4f, 8.3321608736e-3f), -1.6666654611e-1f);
    float sr = fmaf(r * x2, sp, r);
    float cr = fmaf(x2,
                    fmaf(x2,
                         fmaf(x2, fmaf(x2, 2.443315711809948e-5f, -1.388731625493765e-3f),
                              4.166664568298827e-2f),
                         -0.5f),
                    1.0f);
    float ss, cc;
    switch (qn & 3) {
        case 0:  ss = sr;  cc = cr;  break;
        case 1:  ss = cr;  cc = -sr; break;
        case 2:  ss = -sr; cc = -cr; break;
        default: ss = -cr; cc = sr;  break;
    }
    s_out = ss;
    c_out = cc;
}

// ---------------------------------------------------------------------------
// Fused per-head RMSNorm + RoPE + QKV scatter into [B,H,T,HD].
// ---------------------------------------------------------------------------
__global__ void __launch_bounds__(512) norm_rope_kernel(const float* __restrict__ qkv) {
    const int bt = blockIdx.x;
    const int t = bt & (Tc - 1);
    const int b = bt >> 11;
    const int w = threadIdx.x >> 5;
    const int lane = threadIdx.x & 31;

    const float* base = qkv + (size_t)bt * N3c + w * HDc;
    float q1 = base[lane], q2 = base[lane + 32];
    float k1 = base[Cc + lane], k2 = base[Cc + lane + 32];
    float v1 = base[2 * Cc + lane], v2 = base[2 * Cc + lane + 32];

    float sq = q1 * q1 + q2 * q2;
    float sk = k1 * k1 + k2 * k2;
#pragma unroll
    for (int o = 16; o; o >>= 1) {
        sq += __shfl_xor_sync(0xffffffffu, sq, o);
        sk += __shfl_xor_sync(0xffffffffu, sk, o);
    }
    const float eps = 1.1920928955078125e-07f;
    float rq = rsqrtf(sq * (1.f / 64.f) + eps);
    float rk = rsqrtf(sk * (1.f / 64.f) + eps);
    q1 *= rq; q2 *= rq;
    k1 *= rk; k2 *= rk;

    float freq = (float)t * g_invfreq[lane];
    float sn, cs;
    sincos_ref(freq, sn, cs);
    cs = __bfloat162float(__float2bfloat16(cs));
    sn = __bfloat162float(__float2bfloat16(sn));

    float qy1 = q1 * cs + q2 * sn;
    float qy2 = -q1 * sn + q2 * cs;
    float ky1 = k1 * cs + k2 * sn;
    float ky2 = -k1 * sn + k2 * cs;

    size_t obase = ((size_t)(b * Hc + w) * Tc + t) * HDc;
    g_q[obase + lane] = qy1;       g_q[obase + lane + 32] = qy2;
    g_k[obase + lane] = ky1;       g_k[obase + lane + 32] = ky2;
    g_v[obase + lane] = v1;        g_v[obase + lane + 32] = v2;
}

// ---------------------------------------------------------------------------
// Causal flash attention. 64x64 tiles, HD=64, 256 threads, 4x4 per thread.
// ---------------------------------------------------------------------------
#define FMA16(S, A, Bv)                                                     \
    S[0][0] = fmaf(A.x, Bv.x, S[0][0]); S[0][1] = fmaf(A.x, Bv.y, S[0][1]); \
    S[0][2] = fmaf(A.x, Bv.z, S[0][2]); S[0][3] = fmaf(A.x, Bv.w, S[0][3]); \
    S[1][0] = fmaf(A.y, Bv.x, S[1][0]); S[1][1] = fmaf(A.y, Bv.y, S[1][1]); \
    S[1][2] = fmaf(A.y, Bv.z, S[1][2]); S[1][3] = fmaf(A.y, Bv.w, S[1][3]); \
    S[2][0] = fmaf(A.z, Bv.x, S[2][0]); S[2][1] = fmaf(A.z, Bv.y, S[2][1]); \
    S[2][2] = fmaf(A.z, Bv.z, S[2][2]); S[2][3] = fmaf(A.z, Bv.w, S[2][3]); \
    S[3][0] = fmaf(A.w, Bv.x, S[3][0]); S[3][1] = fmaf(A.w, Bv.y, S[3][1]); \
    S[3][2] = fmaf(A.w, Bv.z, S[3][2]); S[3][3] = fmaf(A.w, Bv.w, S[3][3]);

__global__ void __launch_bounds__(256) attn_kernel() {
    __shared__ float QsT[64 * 64];
    __shared__ float KsT[64 * 64];
    __shared__ float Vs[64 * 64];

    const int qi = blockIdx.x;
    const int bh = blockIdx.y;
    const int tid = threadIdx.x;
    const int cg = tid & 15, rg = tid >> 4;
    const int c0 = cg * 4, r0 = rg * 4;
    const size_t base = (size_t)bh * Tc * HDc;
    const int qbase = qi * 64;

    const float* Q = g_q + base;
    const float* K = g_k + base;
    const float* V = g_v + base;

#pragma unroll
    for (int i = 0; i < 4; i++) {
        int e = tid + i * 256;
        int row = e >> 4;
        int col = (e & 15) << 2;
        float4 v = *(const float4*)&Q[(size_t)(qbase + row) * 64 + col];
        QsT[(col + 0) * 64 + row] = v.x * 0.125f;
        QsT[(col + 1) * 64 + row] = v.y * 0.125f;
        QsT[(col + 2) * 64 + row] = v.z * 0.125f;
        QsT[(col + 3) * 64 + row] = v.w * 0.125f;
    }

    float o[4][4];
    float mrow[4], lrow[4];
#pragma unroll
    for (int i = 0; i < 4; i++) {
        mrow[i] = -1e30f;
        lrow[i] = 0.f;
#pragma unroll
        for (int j = 0; j < 4; j++) o[i][j] = 0.f;
    }

    for (int kt = 0; kt <= qi; kt++) {
        const int kbase = kt * 64;
        __syncthreads();
#pragma unroll
        for (int i = 0; i < 4; i++) {
            int e = tid + i * 256;
            int row = e >> 4;
            int col = (e & 15) << 2;
            float4 kv = *(const float4*)&K[(size_t)(kbase + row) * 64 + col];
            KsT[(col + 0) * 64 + row] = kv.x;
            KsT[(col + 1) * 64 + row] = kv.y;
            KsT[(col + 2) * 64 + row] = kv.z;
            KsT[(col + 3) * 64 + row] = kv.w;
            *(float4*)&Vs[row * 64 + col] =
                *(const float4*)&V[(size_t)(kbase + row) * 64 + col];
        }
        __syncthreads();

        float s[4][4];
#pragma unroll
        for (int i = 0; i < 4; i++)
#pragma unroll
            for (int j = 0; j < 4; j++) s[i][j] = 0.f;
#pragma unroll 16
        for (int d = 0; d < 64; d++) {
            float4 a = *(const float4*)&QsT[d * 64 + r0];
            float4 b = *(const float4*)&KsT[d * 64 + c0];
            FMA16(s, a, b)
        }

        if (kt == qi) {
#pragma unroll
            for (int i = 0; i < 4; i++)
#pragma unroll
                for (int j = 0; j < 4; j++)
                    if (c0 + j > r0 + i) s[i][j] = -1e30f;
        }

#pragma unroll
        for (int i = 0; i < 4; i++) {
            float mx = fmaxf(fmaxf(s[i][0], s[i][1]), fmaxf(s[i][2], s[i][3]));
#pragma unroll
            for (int off = 1; off < 16; off <<= 1)
                mx = fmaxf(mx, __shfl_xor_sync(0xffffffffu, mx, off));
            float mnew = fmaxf(mx, mrow[i]);
            float corr = __expf(mrow[i] - mnew);
            mrow[i] = mnew;
            float r = 0.f;
#pragma unroll
            for (int j = 0; j < 4; j++) {
                s[i][j] = __expf(s[i][j] - mnew);
                r += s[i][j];
            }
#pragma unroll
            for (int off = 1; off < 16; off <<= 1)
                r += __shfl_xor_sync(0xffffffffu, r, off);
            lrow[i] = lrow[i] * corr + r;
#pragma unroll
            for (int j = 0; j < 4; j++) o[i][j] *= corr;
        }

        __syncthreads();
        float* PsT = KsT;
#pragma unroll
        for (int j = 0; j < 4; j++) {
            float4 pv = make_float4(s[0][j], s[1][j], s[2][j], s[3][j]);
            *(float4*)&PsT[(c0 + j) * 64 + r0] = pv;
        }
        __syncthreads();

#pragma unroll 16
        for (int n = 0; n < 64; n++) {
            float4 a = *(const float4*)&PsT[n * 64 + r0];
            float4 b = *(const float4*)&Vs[n * 64 + c0];
            FMA16(o, a, b)
        }
    }

    const int b = bh >> 4, h = bh & 15;
#pragma unroll
    for (int i = 0; i < 4; i++) {
        float inv = 1.f / lrow[i];
        int t = qbase + r0 + i;
        float4 v = make_float4(o[i][0] * inv, o[i][1] * inv,
                               o[i][2] * inv, o[i][3] * inv);
        *(float4*)&g_att[((size_t)(b * Tc + t)) * Cc + h * HDc + c0] = v;
    }
}

// ---------------------------------------------------------------------------
// Launch
// ---------------------------------------------------------------------------
extern "C" void kernel_launch(void* const* d_in, const int* in_sizes, int n_in,
                              void* d_out, int out_size) {
    const float* x = (const float*)d_in[0];       // [B*T, C]
    const float* w_attn = (const float*)d_in[1];  // [3C, C]
    const float* w_proj = (const float*)d_in[2];  // [C, C]
    float* out = (float*)d_out;                   // [B*T, C]

    float* qkv_p = nullptr;
    float* att_p = nullptr;
    cudaGetSymbolAddress((void**)&qkv_p, g_qkv);
    cudaGetSymbolAddress((void**)&att_p, g_att);

    __nv_bfloat16 *xhi, *xlo, *wahi, *walo, *wphi, *wplo, *athi, *atlo;
    cudaGetSymbolAddress((void**)&xhi, g_xhi);
    cudaGetSymbolAddress((void**)&xlo, g_xlo);
    cudaGetSymbolAddress((void**)&wahi, g_wahi);
    cudaGetSymbolAddress((void**)&walo, g_walo);
    cudaGetSymbolAddress((void**)&wphi, g_wphi);
    cudaGetSymbolAddress((void**)&wplo, g_wplo);
    cudaGetSymbolAddress((void**)&athi, g_athi);
    cudaGetSymbolAddress((void**)&atlo, g_atlo);

    compute_inv_kernel<<<1, 32>>>();

    // hi/lo splits for x, w_attn, w_proj
    {
        int n4 = (Mc * Cc) / 4;
        split_kernel<<<(n4 + 255) / 256, 256>>>(x, xhi, xlo, n4);
        n4 = (N3c * Cc) / 4;
        split_kernel<<<(n4 + 255) / 256, 256>>>(w_attn, wahi, walo, n4);
        n4 = (Cc * Cc) / 4;
        split_kernel<<<(n4 + 255) / 256, 256>>>(w_proj, wphi, wplo, n4);
    }

    // QKV projection: [8192,1024] x [3072,1024]^T -> [8192,3072]
    {
        dim3 grid(N3c / 128, Mc / 128);
        gemm_mma<<<grid, 256>>>(xhi, xlo, wahi, walo, qkv_p, N3c, Cc);
    }

    norm_rope_kernel<<<Mc, 512>>>(qkv_p);

    {
        dim3 grid(Tc / 64, Bc * Hc);
        attn_kernel<<<grid, 256>>>();
    }

    // split attention output, then out projection
    {
        int n4 = (Mc * Cc) / 4;
        split_kernel<<<(n4 + 255) / 256, 256>>>(att_p, athi, atlo, n4);
        dim3 grid(Cc / 128, Mc / 128);
        gemm_mma<<<grid, 256>>>(athi, atlo, wphi, wplo, out, Cc, Cc);
    }
}

// round 6
// speedup vs baseline: 2.4469x; 1.7370x over previous
#include <cuda_runtime.h>
#include <cuda_bf16.h>
#include <math.h>
#include <stdint.h>

// Problem constants
#define Bc 4
#define Tc 2048
#define Cc 1024
#define Hc 16
#define HDc 64
#define Mc (Bc * Tc)   // 8192
#define N3c (3 * Cc)   // 3072

// ---------------------------------------------------------------------------
// Scratch (static device globals; no runtime allocation allowed)
// ---------------------------------------------------------------------------
__device__ float g_qkv[(size_t)Mc * N3c];          // [B*T, 3C]
__device__ float g_att[(size_t)Mc * Cc];           // [B,T,C]
__device__ float g_invfreq[HDc / 2];

// bf16 hi/lo tensors
__device__ __nv_bfloat16 g_xhi[(size_t)Mc * Cc];
__device__ __nv_bfloat16 g_xlo[(size_t)Mc * Cc];
__device__ __nv_bfloat16 g_wahi[(size_t)N3c * Cc];
__device__ __nv_bfloat16 g_walo[(size_t)N3c * Cc];
__device__ __nv_bfloat16 g_wphi[(size_t)Cc * Cc];
__device__ __nv_bfloat16 g_wplo[(size_t)Cc * Cc];
__device__ __nv_bfloat16 g_athi[(size_t)Mc * Cc];
__device__ __nv_bfloat16 g_atlo[(size_t)Mc * Cc];

// Q/K/V hi-lo, [B,H,T,HD] row-major (Q pre-scaled by 0.125)
#define QKVN ((size_t)Bc * Hc * Tc * HDc)
__device__ __nv_bfloat16 g_qhi[QKVN];
__device__ __nv_bfloat16 g_qlo[QKVN];
__device__ __nv_bfloat16 g_khi[QKVN];
__device__ __nv_bfloat16 g_klo[QKVN];
__device__ __nv_bfloat16 g_vhi[QKVN];
__device__ __nv_bfloat16 g_vlo[QKVN];

// ---------------------------------------------------------------------------
// inv_freq in double — matches 1/10000^(l/32)
// ---------------------------------------------------------------------------
__global__ void compute_inv_kernel() {
    int l = threadIdx.x;
    if (l < HDc / 2) {
        double e = (double)(2 * l) / (double)HDc;
        g_invfreq[l] = (float)(1.0 / pow(10000.0, e));
    }
}

// ---------------------------------------------------------------------------
// fp32 -> bf16 hi/lo split (vectorized by 4)
// ---------------------------------------------------------------------------
__global__ void __launch_bounds__(256) split_kernel(
    const float* __restrict__ src, __nv_bfloat16* __restrict__ hi,
    __nv_bfloat16* __restrict__ lo, int n4) {
    int i = blockIdx.x * 256 + threadIdx.x;
    if (i >= n4) return;
    float4 v = ((const float4*)src)[i];
    float f[4] = {v.x, v.y, v.z, v.w};
    __nv_bfloat16 h[4], l[4];
#pragma unroll
    for (int j = 0; j < 4; j++) {
        h[j] = __float2bfloat16_rn(f[j]);
        l[j] = __float2bfloat16_rn(f[j] - __bfloat162float(h[j]));
    }
    ((uint2*)hi)[i] = *(uint2*)h;
    ((uint2*)lo)[i] = *(uint2*)l;
}

// ---------------------------------------------------------------------------
// mma.sync helpers
// ---------------------------------------------------------------------------
__device__ __forceinline__ void ldmx4(uint32_t* r, uint32_t addr) {
    asm volatile(
        "ldmatrix.sync.aligned.m8n8.x4.shared.b16 {%0,%1,%2,%3}, [%4];"
        : "=r"(r[0]), "=r"(r[1]), "=r"(r[2]), "=r"(r[3])
        : "r"(addr));
}

__device__ __forceinline__ void ldmx4t(uint32_t* r, uint32_t addr) {
    asm volatile(
        "ldmatrix.sync.aligned.m8n8.x4.trans.shared.b16 {%0,%1,%2,%3}, [%4];"
        : "=r"(r[0]), "=r"(r[1]), "=r"(r[2]), "=r"(r[3])
        : "r"(addr));
}

__device__ __forceinline__ void mma_bf16(
    float* d, const uint32_t* a, uint32_t b0, uint32_t b1) {
    asm volatile(
        "mma.sync.aligned.m16n8k16.row.col.f32.bf16.bf16.f32 "
        "{%0,%1,%2,%3}, {%4,%5,%6,%7}, {%8,%9}, {%0,%1,%2,%3};"
        : "+f"(d[0]), "+f"(d[1]), "+f"(d[2]), "+f"(d[3])
        : "r"(a[0]), "r"(a[1]), "r"(a[2]), "r"(a[3]), "r"(b0), "r"(b1));
}

__device__ __forceinline__ uint32_t pkbf2(__nv_bfloat16 a, __nv_bfloat16 b) {
    __nv_bfloat162 v;
    v.x = a;
    v.y = b;
    return *(uint32_t*)&v;
}

// ---------------------------------------------------------------------------
// HMMA GEMM (NT): C[m,n] = sum_k A[m,k]*B[n,k], bf16 hi/lo split (3 MMAs).
// ---------------------------------------------------------------------------
#define PITCH 40

__global__ void __launch_bounds__(256) gemm_mma(
    const __nv_bfloat16* __restrict__ Ahi, const __nv_bfloat16* __restrict__ Alo,
    const __nv_bfloat16* __restrict__ Bhi, const __nv_bfloat16* __restrict__ Blo,
    float* __restrict__ Cm, int N, int K) {
    __shared__ __align__(16) __nv_bfloat16 sAhi[128 * PITCH];
    __shared__ __align__(16) __nv_bfloat16 sAlo[128 * PITCH];
    __shared__ __align__(16) __nv_bfloat16 sBhi[128 * PITCH];
    __shared__ __align__(16) __nv_bfloat16 sBlo[128 * PITCH];

    const int tid = threadIdx.x;
    const int wid = tid >> 5;
    const int lane = tid & 31;
    const int m0 = blockIdx.y * 128;
    const int n0 = blockIdx.x * 128;
    const int wm = wid >> 2;
    const int wn = wid & 3;

    const uint32_t sa_hi = (uint32_t)__cvta_generic_to_shared(sAhi);
    const uint32_t sa_lo = (uint32_t)__cvta_generic_to_shared(sAlo);
    const uint32_t sb_hi = (uint32_t)__cvta_generic_to_shared(sBhi);
    const uint32_t sb_lo = (uint32_t)__cvta_generic_to_shared(sBlo);

    float acc[4][4][4];
#pragma unroll
    for (int i = 0; i < 4; i++)
#pragma unroll
        for (int j = 0; j < 4; j++)
#pragma unroll
            for (int q = 0; q < 4; q++) acc[i][j][q] = 0.f;

    const int lrow = lane & 15;
    const int lcolb = (lane >> 4) * 16;

    const int nchunk = K >> 5;
    for (int c = 0; c < nchunk; c++) {
        const int k0 = c << 5;
#pragma unroll
        for (int i = 0; i < 2; i++) {
            int v = tid + i * 256;
            int row = v >> 2;
            int cq = (v & 3) * 8;
            size_t ga = (size_t)(m0 + row) * K + k0 + cq;
            size_t gb = (size_t)(n0 + row) * K + k0 + cq;
            int so = row * PITCH + cq;
            *(uint4*)(sAhi + so) = *(const uint4*)(Ahi + ga);
            *(uint4*)(sAlo + so) = *(const uint4*)(Alo + ga);
            *(uint4*)(sBhi + so) = *(const uint4*)(Bhi + gb);
            *(uint4*)(sBlo + so) = *(const uint4*)(Blo + gb);
        }
        __syncthreads();

#pragma unroll
        for (int ks = 0; ks < 2; ks++) {
            const uint32_t abase =
                (uint32_t)(((wm * 64 + lrow) * PITCH + ks * 16) * 2) + lcolb;
            const uint32_t bbase =
                (uint32_t)(((wn * 32 + lrow) * PITCH + ks * 16) * 2) + lcolb;

            uint32_t ahi[4][4], alo[4][4];
#pragma unroll
            for (int ti = 0; ti < 4; ti++) {
                uint32_t off = abase + (uint32_t)(ti * 16 * PITCH * 2);
                ldmx4(ahi[ti], sa_hi + off);
                ldmx4(alo[ti], sa_lo + off);
            }
            uint32_t bhi[2][4], blo[2][4];
#pragma unroll
            for (int tg = 0; tg < 2; tg++) {
                uint32_t off = bbase + (uint32_t)(tg * 16 * PITCH * 2);
                ldmx4(bhi[tg], sb_hi + off);
                ldmx4(blo[tg], sb_lo + off);
            }

#pragma unroll
            for (int ti = 0; ti < 4; ti++)
#pragma unroll
                for (int tj = 0; tj < 4; tj++) {
                    const int tg = tj >> 1, sub = tj & 1;
                    mma_bf16(acc[ti][tj], ahi[ti], bhi[tg][sub], bhi[tg][sub + 2]);
                    mma_bf16(acc[ti][tj], ahi[ti], blo[tg][sub], blo[tg][sub + 2]);
                    mma_bf16(acc[ti][tj], alo[ti], bhi[tg][sub], bhi[tg][sub + 2]);
                }
        }
        __syncthreads();
    }

    const int g = lane >> 2;
    const int cq = (lane & 3) * 2;
#pragma unroll
    for (int ti = 0; ti < 4; ti++) {
#pragma unroll
        for (int tj = 0; tj < 4; tj++) {
            int row = m0 + wm * 64 + ti * 16 + g;
            int col = n0 + wn * 32 + tj * 8 + cq;
            *(float2*)&Cm[(size_t)row * N + col] =
                make_float2(acc[ti][tj][0], acc[ti][tj][1]);
            *(float2*)&Cm[(size_t)(row + 8) * N + col] =
                make_float2(acc[ti][tj][2], acc[ti][tj][3]);
        }
    }
}

// ---------------------------------------------------------------------------
// Accurate fp32 sin/cos (Cody-Waite + cephes minimax).
// ---------------------------------------------------------------------------
__device__ __forceinline__ void sincos_ref(float x, float& s_out, float& c_out) {
    float n = rintf(x * 0.63661977236758134f);
    int qn = (int)n;
    float r = fmaf(-n, 1.5707962512969971e+00f, x);
    r = fmaf(-n, 7.5497894158615964e-08f, r);
    r = fmaf(-n, 5.3903025299577648e-15f, r);
    float x2 = r * r;
    float sp = fmaf(x2, fmaf(x2, -1.9515295891e-4f, 8.3321608736e-3f), -1.6666654611e-1f);
    float sr = fmaf(r * x2, sp, r);
    float cr = fmaf(x2,
                    fmaf(x2,
                         fmaf(x2, fmaf(x2, 2.443315711809948e-5f, -1.388731625493765e-3f),
                              4.166664568298827e-2f),
                         -0.5f),
                    1.0f);
    float ss, cc;
    switch (qn & 3) {
        case 0:  ss = sr;  cc = cr;  break;
        case 1:  ss = cr;  cc = -sr; break;
        case 2:  ss = -sr; cc = -cr; break;
        default: ss = -cr; cc = sr;  break;
    }
    s_out = ss;
    c_out = cc;
}

__device__ __forceinline__ void store_split(
    __nv_bfloat16* hi, __nv_bfloat16* lo, size_t idx, float x) {
    __nv_bfloat16 h = __float2bfloat16_rn(x);
    hi[idx] = h;
    lo[idx] = __float2bfloat16_rn(x - __bfloat162float(h));
}

// ---------------------------------------------------------------------------
// Fused per-head RMSNorm + RoPE -> bf16 hi/lo Q(pre-scaled)/K/V [B,H,T,HD]
// ---------------------------------------------------------------------------
__global__ void __launch_bounds__(512) norm_rope_kernel(const float* __restrict__ qkv) {
    const int bt = blockIdx.x;
    const int t = bt & (Tc - 1);
    const int b = bt >> 11;
    const int w = threadIdx.x >> 5;
    const int lane = threadIdx.x & 31;

    const float* base = qkv + (size_t)bt * N3c + w * HDc;
    float q1 = base[lane], q2 = base[lane + 32];
    float k1 = base[Cc + lane], k2 = base[Cc + lane + 32];
    float v1 = base[2 * Cc + lane], v2 = base[2 * Cc + lane + 32];

    float sq = q1 * q1 + q2 * q2;
    float sk = k1 * k1 + k2 * k2;
#pragma unroll
    for (int o = 16; o; o >>= 1) {
        sq += __shfl_xor_sync(0xffffffffu, sq, o);
        sk += __shfl_xor_sync(0xffffffffu, sk, o);
    }
    const float eps = 1.1920928955078125e-07f;
    float rq = rsqrtf(sq * (1.f / 64.f) + eps);
    float rk = rsqrtf(sk * (1.f / 64.f) + eps);
    q1 *= rq; q2 *= rq;
    k1 *= rk; k2 *= rk;

    float freq = (float)t * g_invfreq[lane];
    float sn, cs;
    sincos_ref(freq, sn, cs);
    cs = __bfloat162float(__float2bfloat16(cs));
    sn = __bfloat162float(__float2bfloat16(sn));

    float qy1 = (q1 * cs + q2 * sn) * 0.125f;   // pre-scale by 1/sqrt(HD)
    float qy2 = (-q1 * sn + q2 * cs) * 0.125f;
    float ky1 = k1 * cs + k2 * sn;
    float ky2 = -k1 * sn + k2 * cs;

    size_t ob = ((size_t)(b * Hc + w) * Tc + t) * HDc;
    store_split(g_qhi, g_qlo, ob + lane, qy1);
    store_split(g_qhi, g_qlo, ob + lane + 32, qy2);
    store_split(g_khi, g_klo, ob + lane, ky1);
    store_split(g_khi, g_klo, ob + lane + 32, ky2);
    store_split(g_vhi, g_vlo, ob + lane, v1);
    store_split(g_vhi, g_vlo, ob + lane + 32, v2);
}

// ---------------------------------------------------------------------------
// Tensor-core causal flash attention.
// CTA: 128 q-rows, 8 warps (16 rows each). k-tile = 64. HD=64.
// S and P*V are 3-term bf16 hi/lo split MMAs. smem pitch 72 (conflict-free).
// ---------------------------------------------------------------------------
#define AP 72
#define KB_ (64 * AP * 2)  // bytes per 64-row tile buffer

__global__ void __launch_bounds__(256) attn_mma() {
    __shared__ __align__(16) __nv_bfloat16 sm[4 * 64 * AP];

    const int tid = threadIdx.x;
    const int wid = tid >> 5;
    const int lane = tid & 31;
    const int qi = (Tc / 128 - 1) - blockIdx.x;  // heavy tiles first
    const int bh = blockIdx.y;
    const size_t base = (size_t)bh * Tc * HDc;
    const int q0 = qi * 128;
    const uint32_t smb = (uint32_t)__cvta_generic_to_shared(sm);

    // ---- Stage Q tile (hi in buffers 0-1, lo in buffers 2-3), grab frags ----
    {
        const __nv_bfloat16* Qh = g_qhi + base + (size_t)q0 * HDc;
        const __nv_bfloat16* Ql = g_qlo + base + (size_t)q0 * HDc;
#pragma unroll
        for (int i = 0; i < 4; i++) {
            int v = tid + i * 256;
            int row = v >> 3;
            int col = (v & 7) * 8;
            *(uint4*)(sm + row * AP + col) = *(const uint4*)(Qh + row * HDc + col);
            *(uint4*)(sm + 128 * AP + row * AP + col) =
                *(const uint4*)(Ql + row * HDc + col);
        }
    }
    __syncthreads();

    uint32_t qh[4][4], ql[4][4];
    {
        uint32_t ab = smb + (uint32_t)(((wid * 16 + (lane & 15)) * AP) * 2) +
                      (lane >> 4) * 16;
#pragma unroll
        for (int t = 0; t < 4; t++) {
            ldmx4(qh[t], ab + t * 32);
            ldmx4(ql[t], ab + 128 * AP * 2 + t * 32);
        }
    }
    __syncthreads();

    float o[8][4];
#pragma unroll
    for (int j = 0; j < 8; j++)
#pragma unroll
        for (int q = 0; q < 4; q++) o[j][q] = 0.f;
    float mA = -1e30f, mB = -1e30f, lA = 0.f, lB = 0.f;

    const __nv_bfloat16* Kh = g_khi + base;
    const __nv_bfloat16* Kl = g_klo + base;
    const __nv_bfloat16* Vh = g_vhi + base;
    const __nv_bfloat16* Vl = g_vlo + base;

    const int nkt = 2 * qi + 2;
    for (int kt = 0; kt < nkt; kt++) {
        const int kv0 = kt * 64;
        // ---- Load K,V hi/lo tiles ----
#pragma unroll
        for (int i = 0; i < 2; i++) {
            int v = tid + i * 256;
            int row = v >> 3;
            int col = (v & 7) * 8;
            size_t g = (size_t)(kv0 + row) * HDc + col;
            int so = row * AP + col;
            *(uint4*)(sm + so) = *(const uint4*)(Kh + g);
            *(uint4*)(sm + 64 * AP + so) = *(const uint4*)(Kl + g);
            *(uint4*)(sm + 128 * AP + so) = *(const uint4*)(Vh + g);
            *(uint4*)(sm + 192 * AP + so) = *(const uint4*)(Vl + g);
        }
        __syncthreads();

        // ---- S = Q @ K^T (split 3-term) ----
        float c[8][4];
#pragma unroll
        for (int j = 0; j < 8; j++)
#pragma unroll
            for (int q = 0; q < 4; q++) c[j][q] = 0.f;

#pragma unroll
        for (int t = 0; t < 4; t++) {
#pragma unroll
            for (int tg = 0; tg < 4; tg++) {
                uint32_t kbh[4], kbl[4];
                uint32_t off = smb +
                               (uint32_t)(((tg * 16 + (lane & 15)) * AP) * 2) +
                               (lane >> 4) * 16 + t * 32;
                ldmx4(kbh, off);
                ldmx4(kbl, off + KB_);
                mma_bf16(c[tg * 2 + 0], qh[t], kbh[0], kbh[2]);
                mma_bf16(c[tg * 2 + 0], qh[t], kbl[0], kbl[2]);
                mma_bf16(c[tg * 2 + 0], ql[t], kbh[0], kbh[2]);
                mma_bf16(c[tg * 2 + 1], qh[t], kbh[1], kbh[3]);
                mma_bf16(c[tg * 2 + 1], qh[t], kbl[1], kbl[3]);
                mma_bf16(c[tg * 2 + 1], ql[t], kbh[1], kbh[3]);
            }
        }

        // ---- causal mask (only last two k-tiles touch the diagonal) ----
        const int rA = q0 + wid * 16 + (lane >> 2);
        const int rB = rA + 8;
        if (kt >= 2 * qi) {
#pragma unroll
            for (int j = 0; j < 8; j++) {
                int col0 = kv0 + j * 8 + (lane & 3) * 2;
                if (col0 > rA) c[j][0] = -1e30f;
                if (col0 + 1 > rA) c[j][1] = -1e30f;
                if (col0 > rB) c[j][2] = -1e30f;
                if (col0 + 1 > rB) c[j][3] = -1e30f;
            }
        }

        // ---- online softmax (rows within warp; quad shfl reduce) ----
        float mxA = -1e30f, mxB = -1e30f;
#pragma unroll
        for (int j = 0; j < 8; j++) {
            mxA = fmaxf(mxA, fmaxf(c[j][0], c[j][1]));
            mxB = fmaxf(mxB, fmaxf(c[j][2], c[j][3]));
        }
        mxA = fmaxf(mxA, __shfl_xor_sync(0xffffffffu, mxA, 1));
        mxA = fmaxf(mxA, __shfl_xor_sync(0xffffffffu, mxA, 2));
        mxB = fmaxf(mxB, __shfl_xor_sync(0xffffffffu, mxB, 1));
        mxB = fmaxf(mxB, __shfl_xor_sync(0xffffffffu, mxB, 2));
        float mnA = fmaxf(mA, mxA), mnB = fmaxf(mB, mxB);
        float corrA = __expf(mA - mnA), corrB = __expf(mB - mnB);
        mA = mnA;
        mB = mnB;
        float sA = 0.f, sB = 0.f;
#pragma unroll
        for (int j = 0; j < 8; j++) {
            c[j][0] = __expf(c[j][0] - mnA);
            c[j][1] = __expf(c[j][1] - mnA);
            c[j][2] = __expf(c[j][2] - mnB);
            c[j][3] = __expf(c[j][3] - mnB);
            sA += c[j][0] + c[j][1];
            sB += c[j][2] + c[j][3];
        }
        sA += __shfl_xor_sync(0xffffffffu, sA, 1);
        sA += __shfl_xor_sync(0xffffffffu, sA, 2);
        sB += __shfl_xor_sync(0xffffffffu, sB, 1);
        sB += __shfl_xor_sync(0xffffffffu, sB, 2);
        lA = lA * corrA + sA;
        lB = lB * corrB + sB;
#pragma unroll
        for (int j = 0; j < 8; j++) {
            o[j][0] *= corrA;
            o[j][1] *= corrA;
            o[j][2] *= corrB;
            o[j][3] *= corrB;
        }

        // ---- O += P @ V (P split in registers; V B-frags via ldmatrix.trans) ----
#pragma unroll
        for (int t = 0; t < 4; t++) {
            uint32_t pah[4], pal[4];
#pragma unroll
            for (int e = 0; e < 4; e++) {
                int j = 2 * t + (e >> 1);
                float x = c[j][(e & 1) * 2];
                float y = c[j][(e & 1) * 2 + 1];
                __nv_bfloat16 hx = __float2bfloat16_rn(x);
                __nv_bfloat16 hy = __float2bfloat16_rn(y);
                pah[e] = pkbf2(hx, hy);
                pal[e] = pkbf2(__float2bfloat16_rn(x - __bfloat162float(hx)),
                               __float2bfloat16_rn(y - __bfloat162float(hy)));
            }
#pragma unroll
            for (int dch = 0; dch < 4; dch++) {
                uint32_t vbh[4], vbl[4];
                uint32_t off = smb + 2 * KB_ +
                               (uint32_t)(((t * 16 + (lane & 15)) * AP + dch * 16) * 2) +
                               (lane >> 4) * 16;
                ldmx4t(vbh, off);
                ldmx4t(vbl, off + KB_);
                mma_bf16(o[dch * 2], pah, vbh[0], vbh[1]);
                mma_bf16(o[dch * 2], pah, vbl[0], vbl[1]);
                mma_bf16(o[dch * 2], pal, vbh[0], vbh[1]);
                mma_bf16(o[dch * 2 + 1], pah, vbh[2], vbh[3]);
                mma_bf16(o[dch * 2 + 1], pah, vbl[2], vbl[3]);
                mma_bf16(o[dch * 2 + 1], pal, vbh[2], vbh[3]);
            }
        }
        __syncthreads();
    }

    // ---- epilogue: O /= l, scatter to [B,T,C] ----
    const float iA = 1.f / lA, iB = 1.f / lB;
    const int b = bh >> 4, h = bh & 15;
    const int rA = q0 + wid * 16 + (lane >> 2);
#pragma unroll
    for (int j = 0; j < 8; j++) {
        int d = h * HDc + j * 8 + (lane & 3) * 2;
        *(float2*)&g_att[((size_t)(b * Tc + rA)) * Cc + d] =
            make_float2(o[j][0] * iA, o[j][1] * iA);
        *(float2*)&g_att[((size_t)(b * Tc + rA + 8)) * Cc + d] =
            make_float2(o[j][2] * iB, o[j][3] * iB);
    }
}

// ---------------------------------------------------------------------------
// Launch
// ---------------------------------------------------------------------------
extern "C" void kernel_launch(void* const* d_in, const int* in_sizes, int n_in,
                              void* d_out, int out_size) {
    const float* x = (const float*)d_in[0];
    const float* w_attn = (const float*)d_in[1];
    const float* w_proj = (const float*)d_in[2];
    float* out = (float*)d_out;

    float* qkv_p = nullptr;
    float* att_p = nullptr;
    cudaGetSymbolAddress((void**)&qkv_p, g_qkv);
    cudaGetSymbolAddress((void**)&att_p, g_att);

    __nv_bfloat16 *xhi, *xlo, *wahi, *walo, *wphi, *wplo, *athi, *atlo;
    cudaGetSymbolAddress((void**)&xhi, g_xhi);
    cudaGetSymbolAddress((void**)&xlo, g_xlo);
    cudaGetSymbolAddress((void**)&wahi, g_wahi);
    cudaGetSymbolAddress((void**)&walo, g_walo);
    cudaGetSymbolAddress((void**)&wphi, g_wphi);
    cudaGetSymbolAddress((void**)&wplo, g_wplo);
    cudaGetSymbolAddress((void**)&athi, g_athi);
    cudaGetSymbolAddress((void**)&atlo, g_atlo);

    compute_inv_kernel<<<1, 32>>>();

    {
        int n4 = (Mc * Cc) / 4;
        split_kernel<<<(n4 + 255) / 256, 256>>>(x, xhi, xlo, n4);
        n4 = (N3c * Cc) / 4;
        split_kernel<<<(n4 + 255) / 256, 256>>>(w_attn, wahi, walo, n4);
        n4 = (Cc * Cc) / 4;
        split_kernel<<<(n4 + 255) / 256, 256>>>(w_proj, wphi, wplo, n4);
    }

    {
        dim3 grid(N3c / 128, Mc / 128);
        gemm_mma<<<grid, 256>>>(xhi, xlo, wahi, walo, qkv_p, N3c, Cc);
    }

    norm_rope_kernel<<<Mc, 512>>>(qkv_p);

    {
        dim3 grid(Tc / 128, Bc * Hc);
        attn_mma<<<grid, 256>>>();
    }

    {
        int n4 = (Mc * Cc) / 4;
        split_kernel<<<(n4 + 255) / 256, 256>>>(att_p, athi, atlo, n4);
        dim3 grid(Cc / 128, Mc / 128);
        gemm_mma<<<grid, 256>>>(athi, atlo, wphi, wplo, out, Cc, Cc);
    }
}

// round 7
// speedup vs baseline: 2.5597x; 1.0461x over previous
#include <cuda_runtime.h>
#include <cuda_bf16.h>
#include <math.h>
#include <stdint.h>

// Problem constants
#define Bc 4
#define Tc 2048
#define Cc 1024
#define Hc 16
#define HDc 64
#define Mc (Bc * Tc)   // 8192
#define N3c (3 * Cc)   // 3072

// ---------------------------------------------------------------------------
// Scratch (static device globals; no runtime allocation allowed)
// ---------------------------------------------------------------------------
__device__ float g_qkv[(size_t)Mc * N3c];          // [B*T, 3C]
__device__ float g_invfreq[HDc / 2];

// bf16 hi/lo tensors
__device__ __nv_bfloat16 g_xhi[(size_t)Mc * Cc];
__device__ __nv_bfloat16 g_xlo[(size_t)Mc * Cc];
__device__ __nv_bfloat16 g_wahi[(size_t)N3c * Cc];
__device__ __nv_bfloat16 g_walo[(size_t)N3c * Cc];
__device__ __nv_bfloat16 g_wphi[(size_t)Cc * Cc];
__device__ __nv_bfloat16 g_wplo[(size_t)Cc * Cc];
__device__ __nv_bfloat16 g_athi[(size_t)Mc * Cc];   // attention out hi [B,T,C]
__device__ __nv_bfloat16 g_atlo[(size_t)Mc * Cc];   // attention out lo

// Q/K/V hi-lo, [B,H,T,HD] row-major (Q pre-scaled by 0.125)
#define QKVN ((size_t)Bc * Hc * Tc * HDc)
__device__ __nv_bfloat16 g_qhi[QKVN];
__device__ __nv_bfloat16 g_qlo[QKVN];
__device__ __nv_bfloat16 g_khi[QKVN];
__device__ __nv_bfloat16 g_klo[QKVN];
__device__ __nv_bfloat16 g_vhi[QKVN];
__device__ __nv_bfloat16 g_vlo[QKVN];

// ---------------------------------------------------------------------------
// inv_freq in double — matches 1/10000^(l/32)
// ---------------------------------------------------------------------------
__global__ void compute_inv_kernel() {
    int l = threadIdx.x;
    if (l < HDc / 2) {
        double e = (double)(2 * l) / (double)HDc;
        g_invfreq[l] = (float)(1.0 / pow(10000.0, e));
    }
}

// ---------------------------------------------------------------------------
// fp32 -> bf16 hi/lo split (vectorized by 4)
// ---------------------------------------------------------------------------
__global__ void __launch_bounds__(256) split_kernel(
    const float* __restrict__ src, __nv_bfloat16* __restrict__ hi,
    __nv_bfloat16* __restrict__ lo, int n4) {
    int i = blockIdx.x * 256 + threadIdx.x;
    if (i >= n4) return;
    float4 v = ((const float4*)src)[i];
    float f[4] = {v.x, v.y, v.z, v.w};
    __nv_bfloat16 h[4], l[4];
#pragma unroll
    for (int j = 0; j < 4; j++) {
        h[j] = __float2bfloat16_rn(f[j]);
        l[j] = __float2bfloat16_rn(f[j] - __bfloat162float(h[j]));
    }
    ((uint2*)hi)[i] = *(uint2*)h;
    ((uint2*)lo)[i] = *(uint2*)l;
}

// ---------------------------------------------------------------------------
// mma.sync / cp.async helpers
// ---------------------------------------------------------------------------
__device__ __forceinline__ void ldmx4(uint32_t* r, uint32_t addr) {
    asm volatile(
        "ldmatrix.sync.aligned.m8n8.x4.shared.b16 {%0,%1,%2,%3}, [%4];"
        : "=r"(r[0]), "=r"(r[1]), "=r"(r[2]), "=r"(r[3])
        : "r"(addr));
}

__device__ __forceinline__ void ldmx4t(uint32_t* r, uint32_t addr) {
    asm volatile(
        "ldmatrix.sync.aligned.m8n8.x4.trans.shared.b16 {%0,%1,%2,%3}, [%4];"
        : "=r"(r[0]), "=r"(r[1]), "=r"(r[2]), "=r"(r[3])
        : "r"(addr));
}

__device__ __forceinline__ void mma_bf16(
    float* d, const uint32_t* a, uint32_t b0, uint32_t b1) {
    asm volatile(
        "mma.sync.aligned.m16n8k16.row.col.f32.bf16.bf16.f32 "
        "{%0,%1,%2,%3}, {%4,%5,%6,%7}, {%8,%9}, {%0,%1,%2,%3};"
        : "+f"(d[0]), "+f"(d[1]), "+f"(d[2]), "+f"(d[3])
        : "r"(a[0]), "r"(a[1]), "r"(a[2]), "r"(a[3]), "r"(b0), "r"(b1));
}

__device__ __forceinline__ uint32_t pkbf2(__nv_bfloat16 a, __nv_bfloat16 b) {
    __nv_bfloat162 v;
    v.x = a;
    v.y = b;
    return *(uint32_t*)&v;
}

__device__ __forceinline__ void cpa16(uint32_t s, const void* g) {
    asm volatile("cp.async.cg.shared.global [%0], [%1], 16;" :: "r"(s), "l"(g));
}
#define CP_COMMIT() asm volatile("cp.async.commit_group;" ::: "memory")
#define CP_WAIT1() asm volatile("cp.async.wait_group 1;" ::: "memory")
#define CP_WAIT0() asm volatile("cp.async.wait_group 0;" ::: "memory")

// ---------------------------------------------------------------------------
// HMMA GEMM (NT), cp.async double-buffered.
// C[m,n] = sum_k A[m,k]*B[n,k], bf16 hi/lo split (3 MMAs).
// 128x128 CTA tile, 8 warps (2x4), K-chunks of 32, 2 stages x 40KB dyn smem.
// ---------------------------------------------------------------------------
#define PITCH 40
#define TILE_B (128 * PITCH * 2)      // bytes per [128 x PITCH] bf16 tile
#define STAGE_B (4 * TILE_B)          // 40960 bytes per stage
#define GSMEM (2 * STAGE_B)           // 81920 bytes

__global__ void __launch_bounds__(256) gemm_mma(
    const __nv_bfloat16* __restrict__ Ahi, const __nv_bfloat16* __restrict__ Alo,
    const __nv_bfloat16* __restrict__ Bhi, const __nv_bfloat16* __restrict__ Blo,
    float* __restrict__ Cm, int N, int K) {
    extern __shared__ __align__(16) __nv_bfloat16 dsm[];

    const int tid = threadIdx.x;
    const int wid = tid >> 5;
    const int lane = tid & 31;
    const int m0 = blockIdx.y * 128;
    const int n0 = blockIdx.x * 128;
    const int wm = wid >> 2;
    const int wn = wid & 3;
    const uint32_t smb = (uint32_t)__cvta_generic_to_shared(dsm);

    float acc[4][4][4];
#pragma unroll
    for (int i = 0; i < 4; i++)
#pragma unroll
        for (int j = 0; j < 4; j++)
#pragma unroll
            for (int q = 0; q < 4; q++) acc[i][j][q] = 0.f;

    const int lrow = lane & 15;
    const int lcolb = (lane >> 4) * 16;
    const int nchunk = K >> 5;

    // per-thread load coords (2 rows of 8 bf16 per array per stage)
    const int r0_ = tid >> 2;
    const int cq0 = (tid & 3) * 8;

    // prefetch stage 0
    {
        const int k0 = 0;
#pragma unroll
        for (int i = 0; i < 2; i++) {
            int row = r0_ + i * 64;
            size_t ga = (size_t)(m0 + row) * K + k0 + cq0;
            size_t gb = (size_t)(n0 + row) * K + k0 + cq0;
            uint32_t so = (uint32_t)((row * PITCH + cq0) * 2);
            cpa16(smb + so, Ahi + ga);
            cpa16(smb + TILE_B + so, Alo + ga);
            cpa16(smb + 2 * TILE_B + so, Bhi + gb);
            cpa16(smb + 3 * TILE_B + so, Blo + gb);
        }
    }
    CP_COMMIT();

    for (int c = 0; c < nchunk; c++) {
        if (c + 1 < nchunk) {
            const int k0 = (c + 1) << 5;
            const uint32_t sb = smb + ((c + 1) & 1) * STAGE_B;
#pragma unroll
            for (int i = 0; i < 2; i++) {
                int row = r0_ + i * 64;
                size_t ga = (size_t)(m0 + row) * K + k0 + cq0;
                size_t gb = (size_t)(n0 + row) * K + k0 + cq0;
                uint32_t so = (uint32_t)((row * PITCH + cq0) * 2);
                cpa16(sb + so, Ahi + ga);
                cpa16(sb + TILE_B + so, Alo + ga);
                cpa16(sb + 2 * TILE_B + so, Bhi + gb);
                cpa16(sb + 3 * TILE_B + so, Blo + gb);
            }
            CP_COMMIT();
            CP_WAIT1();
        } else {
            CP_WAIT0();
        }
        __syncthreads();

        const uint32_t sbase = smb + (c & 1) * STAGE_B;
#pragma unroll
        for (int ks = 0; ks < 2; ks++) {
            const uint32_t abase =
                sbase + (uint32_t)(((wm * 64 + lrow) * PITCH + ks * 16) * 2) + lcolb;
            const uint32_t bbase =
                sbase + 2 * TILE_B +
                (uint32_t)(((wn * 32 + lrow) * PITCH + ks * 16) * 2) + lcolb;

            uint32_t ahi[4][4], alo[4][4];
#pragma unroll
            for (int ti = 0; ti < 4; ti++) {
                uint32_t off = abase + (uint32_t)(ti * 16 * PITCH * 2);
                ldmx4(ahi[ti], off);
                ldmx4(alo[ti], off + TILE_B);
            }
            uint32_t bhi[2][4], blo[2][4];
#pragma unroll
            for (int tg = 0; tg < 2; tg++) {
                uint32_t off = bbase + (uint32_t)(tg * 16 * PITCH * 2);
                ldmx4(bhi[tg], off);
                ldmx4(blo[tg], off + TILE_B);
            }

#pragma unroll
            for (int ti = 0; ti < 4; ti++)
#pragma unroll
                for (int tj = 0; tj < 4; tj++) {
                    const int tg = tj >> 1, sub = tj & 1;
                    mma_bf16(acc[ti][tj], ahi[ti], bhi[tg][sub], bhi[tg][sub + 2]);
                    mma_bf16(acc[ti][tj], ahi[ti], blo[tg][sub], blo[tg][sub + 2]);
                    mma_bf16(acc[ti][tj], alo[ti], bhi[tg][sub], bhi[tg][sub + 2]);
                }
        }
        __syncthreads();
    }

    const int g = lane >> 2;
    const int cq = (lane & 3) * 2;
#pragma unroll
    for (int ti = 0; ti < 4; ti++) {
#pragma unroll
        for (int tj = 0; tj < 4; tj++) {
            int row = m0 + wm * 64 + ti * 16 + g;
            int col = n0 + wn * 32 + tj * 8 + cq;
            *(float2*)&Cm[(size_t)row * N + col] =
                make_float2(acc[ti][tj][0], acc[ti][tj][1]);
            *(float2*)&Cm[(size_t)(row + 8) * N + col] =
                make_float2(acc[ti][tj][2], acc[ti][tj][3]);
        }
    }
}

// ---------------------------------------------------------------------------
// Accurate fp32 sin/cos (Cody-Waite + cephes minimax).
// ---------------------------------------------------------------------------
__device__ __forceinline__ void sincos_ref(float x, float& s_out, float& c_out) {
    float n = rintf(x * 0.63661977236758134f);
    int qn = (int)n;
    float r = fmaf(-n, 1.5707962512969971e+00f, x);
    r = fmaf(-n, 7.5497894158615964e-08f, r);
    r = fmaf(-n, 5.3903025299577648e-15f, r);
    float x2 = r * r;
    float sp = fmaf(x2, fmaf(x2, -1.9515295891e-4f, 8.3321608736e-3f), -1.6666654611e-1f);
    float sr = fmaf(r * x2, sp, r);
    float cr = fmaf(x2,
                    fmaf(x2,
                         fmaf(x2, fmaf(x2, 2.443315711809948e-5f, -1.388731625493765e-3f),
                              4.166664568298827e-2f),
                         -0.5f),
                    1.0f);
    float ss, cc;
    switch (qn & 3) {
        case 0:  ss = sr;  cc = cr;  break;
        case 1:  ss = cr;  cc = -sr; break;
        case 2:  ss = -sr; cc = -cr; break;
        default: ss = -cr; cc = sr;  break;
    }
    s_out = ss;
    c_out = cc;
}

__device__ __forceinline__ void store_split(
    __nv_bfloat16* hi, __nv_bfloat16* lo, size_t idx, float x) {
    __nv_bfloat16 h = __float2bfloat16_rn(x);
    hi[idx] = h;
    lo[idx] = __float2bfloat16_rn(x - __bfloat162float(h));
}

// ---------------------------------------------------------------------------
// Fused per-head RMSNorm + RoPE -> bf16 hi/lo Q(pre-scaled)/K/V [B,H,T,HD]
// ---------------------------------------------------------------------------
__global__ void __launch_bounds__(512) norm_rope_kernel(const float* __restrict__ qkv) {
    const int bt = blockIdx.x;
    const int t = bt & (Tc - 1);
    const int b = bt >> 11;
    const int w = threadIdx.x >> 5;
    const int lane = threadIdx.x & 31;

    const float* base = qkv + (size_t)bt * N3c + w * HDc;
    float q1 = base[lane], q2 = base[lane + 32];
    float k1 = base[Cc + lane], k2 = base[Cc + lane + 32];
    float v1 = base[2 * Cc + lane], v2 = base[2 * Cc + lane + 32];

    float sq = q1 * q1 + q2 * q2;
    float sk = k1 * k1 + k2 * k2;
#pragma unroll
    for (int o = 16; o; o >>= 1) {
        sq += __shfl_xor_sync(0xffffffffu, sq, o);
        sk += __shfl_xor_sync(0xffffffffu, sk, o);
    }
    const float eps = 1.1920928955078125e-07f;
    float rq = rsqrtf(sq * (1.f / 64.f) + eps);
    float rk = rsqrtf(sk * (1.f / 64.f) + eps);
    q1 *= rq; q2 *= rq;
    k1 *= rk; k2 *= rk;

    float freq = (float)t * g_invfreq[lane];
    float sn, cs;
    sincos_ref(freq, sn, cs);
    cs = __bfloat162float(__float2bfloat16(cs));
    sn = __bfloat162float(__float2bfloat16(sn));

    float qy1 = (q1 * cs + q2 * sn) * 0.125f;   // pre-scale by 1/sqrt(HD)
    float qy2 = (-q1 * sn + q2 * cs) * 0.125f;
    float ky1 = k1 * cs + k2 * sn;
    float ky2 = -k1 * sn + k2 * cs;

    size_t ob = ((size_t)(b * Hc + w) * Tc + t) * HDc;
    store_split(g_qhi, g_qlo, ob + lane, qy1);
    store_split(g_qhi, g_qlo, ob + lane + 32, qy2);
    store_split(g_khi, g_klo, ob + lane, ky1);
    store_split(g_khi, g_klo, ob + lane + 32, ky2);
    store_split(g_vhi, g_vlo, ob + lane, v1);
    store_split(g_vhi, g_vlo, ob + lane + 32, v2);
}

// ---------------------------------------------------------------------------
// Tensor-core causal flash attention (fused bf16 hi/lo output).
// CTA: 128 q-rows, 8 warps (16 rows each). k-tile = 64. HD=64.
// ---------------------------------------------------------------------------
#define AP 72
#define KB_ (64 * AP * 2)  // bytes per 64-row tile buffer

__global__ void __launch_bounds__(256) attn_mma() {
    __shared__ __align__(16) __nv_bfloat16 sm[4 * 64 * AP];

    const int tid = threadIdx.x;
    const int wid = tid >> 5;
    const int lane = tid & 31;
    const int qi = (Tc / 128 - 1) - blockIdx.x;  // heavy tiles first
    const int bh = blockIdx.y;
    const size_t base = (size_t)bh * Tc * HDc;
    const int q0 = qi * 128;
    const uint32_t smb = (uint32_t)__cvta_generic_to_shared(sm);

    // ---- Stage Q tile (hi then lo), grab frags ----
    {
        const __nv_bfloat16* Qh = g_qhi + base + (size_t)q0 * HDc;
        const __nv_bfloat16* Ql = g_qlo + base + (size_t)q0 * HDc;
#pragma unroll
        for (int i = 0; i < 4; i++) {
            int v = tid + i * 256;
            int row = v >> 3;
            int col = (v & 7) * 8;
            *(uint4*)(sm + row * AP + col) = *(const uint4*)(Qh + row * HDc + col);
            *(uint4*)(sm + 128 * AP + row * AP + col) =
                *(const uint4*)(Ql + row * HDc + col);
        }
    }
    __syncthreads();

    uint32_t qh[4][4], ql[4][4];
    {
        uint32_t ab = smb + (uint32_t)(((wid * 16 + (lane & 15)) * AP) * 2) +
                      (lane >> 4) * 16;
#pragma unroll
        for (int t = 0; t < 4; t++) {
            ldmx4(qh[t], ab + t * 32);
            ldmx4(ql[t], ab + 128 * AP * 2 + t * 32);
        }
    }
    __syncthreads();

    float o[8][4];
#pragma unroll
    for (int j = 0; j < 8; j++)
#pragma unroll
        for (int q = 0; q < 4; q++) o[j][q] = 0.f;
    float mA = -1e30f, mB = -1e30f, lA = 0.f, lB = 0.f;

    const __nv_bfloat16* Kh = g_khi + base;
    const __nv_bfloat16* Kl = g_klo + base;
    const __nv_bfloat16* Vh = g_vhi + base;
    const __nv_bfloat16* Vl = g_vlo + base;

    const int nkt = 2 * qi + 2;
    for (int kt = 0; kt < nkt; kt++) {
        const int kv0 = kt * 64;
#pragma unroll
        for (int i = 0; i < 2; i++) {
            int v = tid + i * 256;
            int row = v >> 3;
            int col = (v & 7) * 8;
            size_t g = (size_t)(kv0 + row) * HDc + col;
            int so = row * AP + col;
            *(uint4*)(sm + so) = *(const uint4*)(Kh + g);
            *(uint4*)(sm + 64 * AP + so) = *(const uint4*)(Kl + g);
            *(uint4*)(sm + 128 * AP + so) = *(const uint4*)(Vh + g);
            *(uint4*)(sm + 192 * AP + so) = *(const uint4*)(Vl + g);
        }
        __syncthreads();

        // ---- S = Q @ K^T (split 3-term) ----
        float c[8][4];
#pragma unroll
        for (int j = 0; j < 8; j++)
#pragma unroll
            for (int q = 0; q < 4; q++) c[j][q] = 0.f;

#pragma unroll
        for (int t = 0; t < 4; t++) {
#pragma unroll
            for (int tg = 0; tg < 4; tg++) {
                uint32_t kbh[4], kbl[4];
                uint32_t off = smb +
                               (uint32_t)(((tg * 16 + (lane & 15)) * AP) * 2) +
                               (lane >> 4) * 16 + t * 32;
                ldmx4(kbh, off);
                ldmx4(kbl, off + KB_);
                mma_bf16(c[tg * 2 + 0], qh[t], kbh[0], kbh[2]);
                mma_bf16(c[tg * 2 + 0], qh[t], kbl[0], kbl[2]);
                mma_bf16(c[tg * 2 + 0], ql[t], kbh[0], kbh[2]);
                mma_bf16(c[tg * 2 + 1], qh[t], kbh[1], kbh[3]);
                mma_bf16(c[tg * 2 + 1], qh[t], kbl[1], kbl[3]);
                mma_bf16(c[tg * 2 + 1], ql[t], kbh[1], kbh[3]);
            }
        }

        // ---- causal mask ----
        const int rA = q0 + wid * 16 + (lane >> 2);
        const int rB = rA + 8;
        if (kt >= 2 * qi) {
#pragma unroll
            for (int j = 0; j < 8; j++) {
                int col0 = kv0 + j * 8 + (lane & 3) * 2;
                if (col0 > rA) c[j][0] = -1e30f;
                if (col0 + 1 > rA) c[j][1] = -1e30f;
                if (col0 > rB) c[j][2] = -1e30f;
                if (col0 + 1 > rB) c[j][3] = -1e30f;
            }
        }

        // ---- online softmax ----
        float mxA = -1e30f, mxB = -1e30f;
#pragma unroll
        for (int j = 0; j < 8; j++) {
            mxA = fmaxf(mxA, fmaxf(c[j][0], c[j][1]));
            mxB = fmaxf(mxB, fmaxf(c[j][2], c[j][3]));
        }
        mxA = fmaxf(mxA, __shfl_xor_sync(0xffffffffu, mxA, 1));
        mxA = fmaxf(mxA, __shfl_xor_sync(0xffffffffu, mxA, 2));
        mxB = fmaxf(mxB, __shfl_xor_sync(0xffffffffu, mxB, 1));
        mxB = fmaxf(mxB, __shfl_xor_sync(0xffffffffu, mxB, 2));
        float mnA = fmaxf(mA, mxA), mnB = fmaxf(mB, mxB);
        float corrA = __expf(mA - mnA), corrB = __expf(mB - mnB);
        mA = mnA;
        mB = mnB;
        float sA = 0.f, sB = 0.f;
#pragma unroll
        for (int j = 0; j < 8; j++) {
            c[j][0] = __expf(c[j][0] - mnA);
            c[j][1] = __expf(c[j][1] - mnA);
            c[j][2] = __expf(c[j][2] - mnB);
            c[j][3] = __expf(c[j][3] - mnB);
            sA += c[j][0] + c[j][1];
            sB += c[j][2] + c[j][3];
        }
        sA += __shfl_xor_sync(0xffffffffu, sA, 1);
        sA += __shfl_xor_sync(0xffffffffu, sA, 2);
        sB += __shfl_xor_sync(0xffffffffu, sB, 1);
        sB += __shfl_xor_sync(0xffffffffu, sB, 2);
        lA = lA * corrA + sA;
        lB = lB * corrB + sB;
#pragma unroll
        for (int j = 0; j < 8; j++) {
            o[j][0] *= corrA;
            o[j][1] *= corrA;
            o[j][2] *= corrB;
            o[j][3] *= corrB;
        }

        // ---- O += P @ V ----
#pragma unroll
        for (int t = 0; t < 4; t++) {
            uint32_t pah[4], pal[4];
#pragma unroll
            for (int e = 0; e < 4; e++) {
                int j = 2 * t + (e >> 1);
                float x = c[j][(e & 1) * 2];
                float y = c[j][(e & 1) * 2 + 1];
                __nv_bfloat16 hx = __float2bfloat16_rn(x);
                __nv_bfloat16 hy = __float2bfloat16_rn(y);
                pah[e] = pkbf2(hx, hy);
                pal[e] = pkbf2(__float2bfloat16_rn(x - __bfloat162float(hx)),
                               __float2bfloat16_rn(y - __bfloat162float(hy)));
            }
#pragma unroll
            for (int dch = 0; dch < 4; dch++) {
                uint32_t vbh[4], vbl[4];
                uint32_t off = smb + 2 * KB_ +
                               (uint32_t)(((t * 16 + (lane & 15)) * AP + dch * 16) * 2) +
                               (lane >> 4) * 16;
                ldmx4t(vbh, off);
                ldmx4t(vbl, off + KB_);
                mma_bf16(o[dch * 2], pah, vbh[0], vbh[1]);
                mma_bf16(o[dch * 2], pah, vbl[0], vbl[1]);
                mma_bf16(o[dch * 2], pal, vbh[0], vbh[1]);
                mma_bf16(o[dch * 2 + 1], pah, vbh[2], vbh[3]);
                mma_bf16(o[dch * 2 + 1], pah, vbl[2], vbl[3]);
                mma_bf16(o[dch * 2 + 1], pal, vbh[2], vbh[3]);
            }
        }
        __syncthreads();
    }

    // ---- epilogue: O /= l, split to bf16 hi/lo, scatter to [B,T,C] ----
    const float iA = 1.f / lA, iB = 1.f / lB;
    const int b = bh >> 4, h = bh & 15;
    const int rA = q0 + wid * 16 + (lane >> 2);
#pragma unroll
    for (int j = 0; j < 8; j++) {
        int d = h * HDc + j * 8 + (lane & 3) * 2;
        size_t iA0 = ((size_t)(b * Tc + rA)) * Cc + d;
        size_t iB0 = ((size_t)(b * Tc + rA + 8)) * Cc + d;
        float x0 = o[j][0] * iA, x1 = o[j][1] * iA;
        float x2 = o[j][2] * iB, x3 = o[j][3] * iB;
        __nv_bfloat16 h0 = __float2bfloat16_rn(x0), h1 = __float2bfloat16_rn(x1);
        __nv_bfloat16 h2 = __float2bfloat16_rn(x2), h3 = __float2bfloat16_rn(x3);
        *(uint32_t*)&g_athi[iA0] = pkbf2(h0, h1);
        *(uint32_t*)&g_atlo[iA0] =
            pkbf2(__float2bfloat16_rn(x0 - __bfloat162float(h0)),
                  __float2bfloat16_rn(x1 - __bfloat162float(h1)));
        *(uint32_t*)&g_athi[iB0] = pkbf2(h2, h3);
        *(uint32_t*)&g_atlo[iB0] =
            pkbf2(__float2bfloat16_rn(x2 - __bfloat162float(h2)),
                  __float2bfloat16_rn(x3 - __bfloat162float(h3)));
    }
}

// ---------------------------------------------------------------------------
// Launch
// ---------------------------------------------------------------------------
extern "C" void kernel_launch(void* const* d_in, const int* in_sizes, int n_in,
                              void* d_out, int out_size) {
    const float* x = (const float*)d_in[0];
    const float* w_attn = (const float*)d_in[1];
    const float* w_proj = (const float*)d_in[2];
    float* out = (float*)d_out;

    float* qkv_p = nullptr;
    cudaGetSymbolAddress((void**)&qkv_p, g_qkv);

    __nv_bfloat16 *xhi, *xlo, *wahi, *walo, *wphi, *wplo, *athi, *atlo;
    cudaGetSymbolAddress((void**)&xhi, g_xhi);
    cudaGetSymbolAddress((void**)&xlo, g_xlo);
    cudaGetSymbolAddress((void**)&wahi, g_wahi);
    cudaGetSymbolAddress((void**)&walo, g_walo);
    cudaGetSymbolAddress((void**)&wphi, g_wphi);
    cudaGetSymbolAddress((void**)&wplo, g_wplo);
    cudaGetSymbolAddress((void**)&athi, g_athi);
    cudaGetSymbolAddress((void**)&atlo, g_atlo);

    cudaFuncSetAttribute(gemm_mma, cudaFuncAttributeMaxDynamicSharedMemorySize,
                         GSMEM);

    compute_inv_kernel<<<1, 32>>>();

    {
        int n4 = (Mc * Cc) / 4;
        split_kernel<<<(n4 + 255) / 256, 256>>>(x, xhi, xlo, n4);
        n4 = (N3c * Cc) / 4;
        split_kernel<<<(n4 + 255) / 256, 256>>>(w_attn, wahi, walo, n4);
        n4 = (Cc * Cc) / 4;
        split_kernel<<<(n4 + 255) / 256, 256>>>(w_proj, wphi, wplo, n4);
    }

    {
        dim3 grid(N3c / 128, Mc / 128);
        gemm_mma<<<grid, 256, GSMEM>>>(xhi, xlo, wahi, walo, qkv_p, N3c, Cc);
    }

    norm_rope_kernel<<<Mc, 512>>>(qkv_p);

    {
        dim3 grid(Tc / 128, Bc * Hc);
        attn_mma<<<grid, 256>>>();
    }

    {
        dim3 grid(Cc / 128, Mc / 128);
        gemm_mma<<<grid, 256, GSMEM>>>(athi, atlo, wphi, wplo, out, Cc, Cc);
    }
}

// round 9
// speedup vs baseline: 2.6710x; 1.0435x over previous
#include <cuda_runtime.h>
#include <cuda_bf16.h>
#include <math.h>
#include <stdint.h>

// Problem constants
#define Bc 4
#define Tc 2048
#define Cc 1024
#define Hc 16
#define HDc 64
#define Mc (Bc * Tc)   // 8192
#define N3c (3 * Cc)   // 3072

// ---------------------------------------------------------------------------
// Scratch (static device globals; no runtime allocation allowed)
// ---------------------------------------------------------------------------
__device__ float g_qkv[(size_t)Mc * N3c];          // [B*T, 3C]
__device__ float g_invfreq[HDc / 2];

// bf16 hi/lo tensors
__device__ __nv_bfloat16 g_xhi[(size_t)Mc * Cc];
__device__ __nv_bfloat16 g_xlo[(size_t)Mc * Cc];
__device__ __nv_bfloat16 g_wahi[(size_t)N3c * Cc];
__device__ __nv_bfloat16 g_walo[(size_t)N3c * Cc];
__device__ __nv_bfloat16 g_wphi[(size_t)Cc * Cc];
__device__ __nv_bfloat16 g_wplo[(size_t)Cc * Cc];
__device__ __nv_bfloat16 g_athi[(size_t)Mc * Cc];   // attention out hi [B,T,C]
__device__ __nv_bfloat16 g_atlo[(size_t)Mc * Cc];   // attention out lo

// Q/K/V hi-lo, [B,H,T,HD] row-major (Q pre-scaled by 0.125)
#define QKVN ((size_t)Bc * Hc * Tc * HDc)
__device__ __nv_bfloat16 g_qhi[QKVN];
__device__ __nv_bfloat16 g_qlo[QKVN];
__device__ __nv_bfloat16 g_khi[QKVN];
__device__ __nv_bfloat16 g_klo[QKVN];
__device__ __nv_bfloat16 g_vhi[QKVN];
__device__ __nv_bfloat16 g_vlo[QKVN];

// ---------------------------------------------------------------------------
// inv_freq in double — matches 1/10000^(l/32)
// ---------------------------------------------------------------------------
__global__ void compute_inv_kernel() {
    int l = threadIdx.x;
    if (l < HDc / 2) {
        double e = (double)(2 * l) / (double)HDc;
        g_invfreq[l] = (float)(1.0 / pow(10000.0, e));
    }
}

// ---------------------------------------------------------------------------
// fp32 -> bf16 hi/lo split (vectorized by 4)
// ---------------------------------------------------------------------------
__global__ void __launch_bounds__(256) split_kernel(
    const float* __restrict__ src, __nv_bfloat16* __restrict__ hi,
    __nv_bfloat16* __restrict__ lo, int n4) {
    int i = blockIdx.x * 256 + threadIdx.x;
    if (i >= n4) return;
    float4 v = ((const float4*)src)[i];
    float f[4] = {v.x, v.y, v.z, v.w};
    __nv_bfloat16 h[4], l[4];
#pragma unroll
    for (int j = 0; j < 4; j++) {
        h[j] = __float2bfloat16_rn(f[j]);
        l[j] = __float2bfloat16_rn(f[j] - __bfloat162float(h[j]));
    }
    ((uint2*)hi)[i] = *(uint2*)h;
    ((uint2*)lo)[i] = *(uint2*)l;
}

// ---------------------------------------------------------------------------
// mma.sync / cp.async helpers
// ---------------------------------------------------------------------------
__device__ __forceinline__ void ldmx4(uint32_t* r, uint32_t addr) {
    asm volatile(
        "ldmatrix.sync.aligned.m8n8.x4.shared.b16 {%0,%1,%2,%3}, [%4];"
        : "=r"(r[0]), "=r"(r[1]), "=r"(r[2]), "=r"(r[3])
        : "r"(addr));
}

__device__ __forceinline__ void ldmx4t(uint32_t* r, uint32_t addr) {
    asm volatile(
        "ldmatrix.sync.aligned.m8n8.x4.trans.shared.b16 {%0,%1,%2,%3}, [%4];"
        : "=r"(r[0]), "=r"(r[1]), "=r"(r[2]), "=r"(r[3])
        : "r"(addr));
}

__device__ __forceinline__ void mma_bf16(
    float* d, const uint32_t* a, uint32_t b0, uint32_t b1) {
    asm volatile(
        "mma.sync.aligned.m16n8k16.row.col.f32.bf16.bf16.f32 "
        "{%0,%1,%2,%3}, {%4,%5,%6,%7}, {%8,%9}, {%0,%1,%2,%3};"
        : "+f"(d[0]), "+f"(d[1]), "+f"(d[2]), "+f"(d[3])
        : "r"(a[0]), "r"(a[1]), "r"(a[2]), "r"(a[3]), "r"(b0), "r"(b1));
}

__device__ __forceinline__ uint32_t pkbf2(__nv_bfloat16 a, __nv_bfloat16 b) {
    __nv_bfloat162 v;
    v.x = a;
    v.y = b;
    return *(uint32_t*)&v;
}

__device__ __forceinline__ void cpa16(uint32_t s, const void* g) {
    asm volatile("cp.async.cg.shared.global [%0], [%1], 16;" :: "r"(s), "l"(g));
}
#define CP_COMMIT() asm volatile("cp.async.commit_group;" ::: "memory")
#define CP_WAIT1() asm volatile("cp.async.wait_group 1;" ::: "memory")
#define CP_WAIT0() asm volatile("cp.async.wait_group 0;" ::: "memory")

// ---------------------------------------------------------------------------
// HMMA GEMM (NT), cp.async double-buffered.
// ---------------------------------------------------------------------------
#define PITCH 40
#define TILE_B (128 * PITCH * 2)
#define STAGE_B (4 * TILE_B)
#define GSMEM (2 * STAGE_B)

__global__ void __launch_bounds__(256) gemm_mma(
    const __nv_bfloat16* __restrict__ Ahi, const __nv_bfloat16* __restrict__ Alo,
    const __nv_bfloat16* __restrict__ Bhi, const __nv_bfloat16* __restrict__ Blo,
    float* __restrict__ Cm, int N, int K) {
    extern __shared__ __align__(16) __nv_bfloat16 dsm[];

    const int tid = threadIdx.x;
    const int wid = tid >> 5;
    const int lane = tid & 31;
    const int m0 = blockIdx.y * 128;
    const int n0 = blockIdx.x * 128;
    const int wm = wid >> 2;
    const int wn = wid & 3;
    const uint32_t smb = (uint32_t)__cvta_generic_to_shared(dsm);

    float acc[4][4][4];
#pragma unroll
    for (int i = 0; i < 4; i++)
#pragma unroll
        for (int j = 0; j < 4; j++)
#pragma unroll
            for (int q = 0; q < 4; q++) acc[i][j][q] = 0.f;

    const int lrow = lane & 15;
    const int lcolb = (lane >> 4) * 16;
    const int nchunk = K >> 5;

    const int r0_ = tid >> 2;
    const int cq0 = (tid & 3) * 8;

    {
#pragma unroll
        for (int i = 0; i < 2; i++) {
            int row = r0_ + i * 64;
            size_t ga = (size_t)(m0 + row) * K + cq0;
            size_t gb = (size_t)(n0 + row) * K + cq0;
            uint32_t so = (uint32_t)((row * PITCH + cq0) * 2);
            cpa16(smb + so, Ahi + ga);
            cpa16(smb + TILE_B + so, Alo + ga);
            cpa16(smb + 2 * TILE_B + so, Bhi + gb);
            cpa16(smb + 3 * TILE_B + so, Blo + gb);
        }
    }
    CP_COMMIT();

    for (int c = 0; c < nchunk; c++) {
        if (c + 1 < nchunk) {
            const int k0 = (c + 1) << 5;
            const uint32_t sb = smb + ((c + 1) & 1) * STAGE_B;
#pragma unroll
            for (int i = 0; i < 2; i++) {
                int row = r0_ + i * 64;
                size_t ga = (size_t)(m0 + row) * K + k0 + cq0;
                size_t gb = (size_t)(n0 + row) * K + k0 + cq0;
                uint32_t so = (uint32_t)((row * PITCH + cq0) * 2);
                cpa16(sb + so, Ahi + ga);
                cpa16(sb + TILE_B + so, Alo + ga);
                cpa16(sb + 2 * TILE_B + so, Bhi + gb);
                cpa16(sb + 3 * TILE_B + so, Blo + gb);
            }
            CP_COMMIT();
            CP_WAIT1();
        } else {
            CP_WAIT0();
        }
        __syncthreads();

        const uint32_t sbase = smb + (c & 1) * STAGE_B;
#pragma unroll
        for (int ks = 0; ks < 2; ks++) {
            const uint32_t abase =
                sbase + (uint32_t)(((wm * 64 + lrow) * PITCH + ks * 16) * 2) + lcolb;
            const uint32_t bbase =
                sbase + 2 * TILE_B +
                (uint32_t)(((wn * 32 + lrow) * PITCH + ks * 16) * 2) + lcolb;

            uint32_t ahi[4][4], alo[4][4];
#pragma unroll
            for (int ti = 0; ti < 4; ti++) {
                uint32_t off = abase + (uint32_t)(ti * 16 * PITCH * 2);
                ldmx4(ahi[ti], off);
                ldmx4(alo[ti], off + TILE_B);
            }
            uint32_t bhi[2][4], blo[2][4];
#pragma unroll
            for (int tg = 0; tg < 2; tg++) {
                uint32_t off = bbase + (uint32_t)(tg * 16 * PITCH * 2);
                ldmx4(bhi[tg], off);
                ldmx4(blo[tg], off + TILE_B);
            }

#pragma unroll
            for (int ti = 0; ti < 4; ti++)
#pragma unroll
                for (int tj = 0; tj < 4; tj++) {
                    const int tg = tj >> 1, sub = tj & 1;
                    mma_bf16(acc[ti][tj], ahi[ti], bhi[tg][sub], bhi[tg][sub + 2]);
                    mma_bf16(acc[ti][tj], ahi[ti], blo[tg][sub], blo[tg][sub + 2]);
                    mma_bf16(acc[ti][tj], alo[ti], bhi[tg][sub], bhi[tg][sub + 2]);
                }
        }
        __syncthreads();
    }

    const int g = lane >> 2;
    const int cq = (lane & 3) * 2;
#pragma unroll
    for (int ti = 0; ti < 4; ti++) {
#pragma unroll
        for (int tj = 0; tj < 4; tj++) {
            int row = m0 + wm * 64 + ti * 16 + g;
            int col = n0 + wn * 32 + tj * 8 + cq;
            *(float2*)&Cm[(size_t)row * N + col] =
                make_float2(acc[ti][tj][0], acc[ti][tj][1]);
            *(float2*)&Cm[(size_t)(row + 8) * N + col] =
                make_float2(acc[ti][tj][2], acc[ti][tj][3]);
        }
    }
}

// ---------------------------------------------------------------------------
// Accurate fp32 sin/cos (Cody-Waite + cephes minimax).
// ---------------------------------------------------------------------------
__device__ __forceinline__ void sincos_ref(float x, float& s_out, float& c_out) {
    float n = rintf(x * 0.63661977236758134f);
    int qn = (int)n;
    float r = fmaf(-n, 1.5707962512969971e+00f, x);
    r = fmaf(-n, 7.5497894158615964e-08f, r);
    r = fmaf(-n, 5.3903025299577648e-15f, r);
    float x2 = r * r;
    float sp = fmaf(x2, fmaf(x2, -1.9515295891e-4f, 8.3321608736e-3f), -1.6666654611e-1f);
    float sr = fmaf(r * x2, sp, r);
    float cr = fmaf(x2,
                    fmaf(x2,
                         fmaf(x2, fmaf(x2, 2.443315711809948e-5f, -1.388731625493765e-3f),
                              4.166664568298827e-2f),
                         -0.5f),
                    1.0f);
    float ss, cc;
    switch (qn & 3) {
        case 0:  ss = sr;  cc = cr;  break;
        case 1:  ss = cr;  cc = -sr; break;
        case 2:  ss = -sr; cc = -cr; break;
        default: ss = -cr; cc = sr;  break;
    }
    s_out = ss;
    c_out = cc;
}

__device__ __forceinline__ void store_split(
    __nv_bfloat16* hi, __nv_bfloat16* lo, size_t idx, float x) {
    __nv_bfloat16 h = __float2bfloat16_rn(x);
    hi[idx] = h;
    lo[idx] = __float2bfloat16_rn(x - __bfloat162float(h));
}

// ---------------------------------------------------------------------------
// Fused per-head RMSNorm + RoPE -> bf16 hi/lo Q(pre-scaled)/K/V [B,H,T,HD]
// ---------------------------------------------------------------------------
__global__ void __launch_bounds__(512) norm_rope_kernel(const float* __restrict__ qkv) {
    const int bt = blockIdx.x;
    const int t = bt & (Tc - 1);
    const int b = bt >> 11;
    const int w = threadIdx.x >> 5;
    const int lane = threadIdx.x & 31;

    const float* base = qkv + (size_t)bt * N3c + w * HDc;
    float q1 = base[lane], q2 = base[lane + 32];
    float k1 = base[Cc + lane], k2 = base[Cc + lane + 32];
    float v1 = base[2 * Cc + lane], v2 = base[2 * Cc + lane + 32];

    float sq = q1 * q1 + q2 * q2;
    float sk = k1 * k1 + k2 * k2;
#pragma unroll
    for (int o = 16; o; o >>= 1) {
        sq += __shfl_xor_sync(0xffffffffu, sq, o);
        sk += __shfl_xor_sync(0xffffffffu, sk, o);
    }
    const float eps = 1.1920928955078125e-07f;
    float rq = rsqrtf(sq * (1.f / 64.f) + eps);
    float rk = rsqrtf(sk * (1.f / 64.f) + eps);
    q1 *= rq; q2 *= rq;
    k1 *= rk; k2 *= rk;

    float freq = (float)t * g_invfreq[lane];
    float sn, cs;
    sincos_ref(freq, sn, cs);
    cs = __bfloat162float(__float2bfloat16(cs));
    sn = __bfloat162float(__float2bfloat16(sn));

    float qy1 = (q1 * cs + q2 * sn) * 0.125f;   // pre-scale by 1/sqrt(HD)
    float qy2 = (-q1 * sn + q2 * cs) * 0.125f;
    float ky1 = k1 * cs + k2 * sn;
    float ky2 = -k1 * sn + k2 * cs;

    size_t ob = ((size_t)(b * Hc + w) * Tc + t) * HDc;
    store_split(g_qhi, g_qlo, ob + lane, qy1);
    store_split(g_qhi, g_qlo, ob + lane + 32, qy2);
    store_split(g_khi, g_klo, ob + lane, ky1);
    store_split(g_khi, g_klo, ob + lane + 32, ky2);
    store_split(g_vhi, g_vlo, ob + lane, v1);
    store_split(g_vhi, g_vlo, ob + lane + 32, v2);
}

// ---------------------------------------------------------------------------
// Tensor-core causal flash attention, cp.async double-buffered K/V pipeline.
// CTA: 128 q-rows, 8 warps (16 rows each). k-tile = 64. HD=64.
// Dynamic smem: Q region (36864B) + 2 stages x 36864B = 110592B.
// ---------------------------------------------------------------------------
#define AP 72
#define KB_ (64 * AP * 2)       // 9216 bytes per 64-row tensor tile
#define ASTAGE (4 * KB_)        // 36864 bytes per stage (Kh,Kl,Vh,Vl)
#define AQREG (2 * 128 * AP * 2)  // 36864 bytes (Qh,Ql)
#define ASMEM (AQREG + 2 * ASTAGE)  // 110592

__global__ void __launch_bounds__(256) attn_mma() {
    extern __shared__ __align__(16) __nv_bfloat16 asm_[];

    const int tid = threadIdx.x;
    const int wid = tid >> 5;
    const int lane = tid & 31;
    const int qi = (Tc / 128 - 1) - blockIdx.x;  // heavy tiles first
    const int bh = blockIdx.y;
    const size_t base = (size_t)bh * Tc * HDc;
    const int q0 = qi * 128;
    const uint32_t smbq = (uint32_t)__cvta_generic_to_shared(asm_);
    const uint32_t smbs = smbq + AQREG;

    const __nv_bfloat16* Kh = g_khi + base;
    const __nv_bfloat16* Kl = g_klo + base;
    const __nv_bfloat16* Vh = g_vhi + base;
    const __nv_bfloat16* Vl = g_vlo + base;

    const int lr_ = tid >> 3;        // 0..31
    const int lc_ = (tid & 7) * 8;   // 0..56

    // ---- async-load Q (group 0) ----
    {
        const __nv_bfloat16* Qh = g_qhi + base + (size_t)q0 * HDc;
        const __nv_bfloat16* Ql = g_qlo + base + (size_t)q0 * HDc;
#pragma unroll
        for (int i = 0; i < 4; i++) {
            int row = lr_ + i * 32;  // 0..127
            uint32_t so = (uint32_t)((row * AP + lc_) * 2);
            cpa16(smbq + so, Qh + (size_t)row * HDc + lc_);
            cpa16(smbq + 128 * AP * 2 + so, Ql + (size_t)row * HDc + lc_);
        }
    }
    CP_COMMIT();

    // ---- prefetch k-tile 0 (group 1) ----
    {
#pragma unroll
        for (int i = 0; i < 2; i++) {
            int row = lr_ + i * 32;  // 0..63
            size_t g = (size_t)row * HDc + lc_;
            uint32_t so = (uint32_t)((row * AP + lc_) * 2);
            cpa16(smbs + so, Kh + g);
            cpa16(smbs + KB_ + so, Kl + g);
            cpa16(smbs + 2 * KB_ + so, Vh + g);
            cpa16(smbs + 3 * KB_ + so, Vl + g);
        }
    }
    CP_COMMIT();

    // ---- Q visible (<=1 group outstanding), extract fragments ----
    CP_WAIT1();
    __syncthreads();

    uint32_t qh[4][4], ql[4][4];
    {
        uint32_t ab = smbq + (uint32_t)(((wid * 16 + (lane & 15)) * AP) * 2) +
                      (lane >> 4) * 16;
#pragma unroll
        for (int t = 0; t < 4; t++) {
            ldmx4(qh[t], ab + t * 32);
            ldmx4(ql[t], ab + 128 * AP * 2 + t * 32);
        }
    }

    float o[8][4];
#pragma unroll
    for (int j = 0; j < 8; j++)
#pragma unroll
        for (int q = 0; q < 4; q++) o[j][q] = 0.f;
    float mA = -1e30f, mB = -1e30f, lA = 0.f, lB = 0.f;

    const int nkt = 2 * qi + 2;
    for (int kt = 0; kt < nkt; kt++) {
        // ---- prefetch kt+1 into other stage, then wait for kt's data ----
        if (kt + 1 < nkt) {
            const int kv1 = (kt + 1) * 64;
            const uint32_t sb = smbs + ((kt + 1) & 1) * ASTAGE;
#pragma unroll
            for (int i = 0; i < 2; i++) {
                int row = lr_ + i * 32;
                size_t g = (size_t)(kv1 + row) * HDc + lc_;
                uint32_t so = (uint32_t)((row * AP + lc_) * 2);
                cpa16(sb + so, Kh + g);
                cpa16(sb + KB_ + so, Kl + g);
                cpa16(sb + 2 * KB_ + so, Vh + g);
                cpa16(sb + 3 * KB_ + so, Vl + g);
            }
            CP_COMMIT();
            CP_WAIT1();
        } else {
            CP_WAIT0();
        }
        __syncthreads();

        const int kv0 = kt * 64;
        const uint32_t sbase = smbs + (kt & 1) * ASTAGE;

        // ---- S = Q @ K^T (split 3-term) ----
        float c[8][4];
#pragma unroll
        for (int j = 0; j < 8; j++)
#pragma unroll
            for (int q = 0; q < 4; q++) c[j][q] = 0.f;

#pragma unroll
        for (int t = 0; t < 4; t++) {
#pragma unroll
            for (int tg = 0; tg < 4; tg++) {
                uint32_t kbh[4], kbl[4];
                uint32_t off = sbase +
                               (uint32_t)(((tg * 16 + (lane & 15)) * AP) * 2) +
                               (lane >> 4) * 16 + t * 32;
                ldmx4(kbh, off);
                ldmx4(kbl, off + KB_);
                mma_bf16(c[tg * 2 + 0], qh[t], kbh[0], kbh[2]);
                mma_bf16(c[tg * 2 + 0], qh[t], kbl[0], kbl[2]);
                mma_bf16(c[tg * 2 + 0], ql[t], kbh[0], kbh[2]);
                mma_bf16(c[tg * 2 + 1], qh[t], kbh[1], kbh[3]);
                mma_bf16(c[tg * 2 + 1], qh[t], kbl[1], kbl[3]);
                mma_bf16(c[tg * 2 + 1], ql[t], kbh[1], kbh[3]);
            }
        }

        // ---- causal mask ----
        const int rA = q0 + wid * 16 + (lane >> 2);
        const int rB = rA + 8;
        if (kt >= 2 * qi) {
#pragma unroll
            for (int j = 0; j < 8; j++) {
                int col0 = kv0 + j * 8 + (lane & 3) * 2;
                if (col0 > rA) c[j][0] = -1e30f;
                if (col0 + 1 > rA) c[j][1] = -1e30f;
                if (col0 > rB) c[j][2] = -1e30f;
                if (col0 + 1 > rB) c[j][3] = -1e30f;
            }
        }

        // ---- online softmax ----
        float mxA = -1e30f, mxB = -1e30f;
#pragma unroll
        for (int j = 0; j < 8; j++) {
            mxA = fmaxf(mxA, fmaxf(c[j][0], c[j][1]));
            mxB = fmaxf(mxB, fmaxf(c[j][2], c[j][3]));
        }
        mxA = fmaxf(mxA, __shfl_xor_sync(0xffffffffu, mxA, 1));
        mxA = fmaxf(mxA, __shfl_xor_sync(0xffffffffu, mxA, 2));
        mxB = fmaxf(mxB, __shfl_xor_sync(0xffffffffu, mxB, 1));
        mxB = fmaxf(mxB, __shfl_xor_sync(0xffffffffu, mxB, 2));
        float mnA = fmaxf(mA, mxA), mnB = fmaxf(mB, mxB);
        float corrA = __expf(mA - mnA), corrB = __expf(mB - mnB);
        mA = mnA;
        mB = mnB;
        float sA = 0.f, sB = 0.f;
#pragma unroll
        for (int j = 0; j < 8; j++) {
            c[j][0] = __expf(c[j][0] - mnA);
            c[j][1] = __expf(c[j][1] - mnA);
            c[j][2] = __expf(c[j][2] - mnB);
            c[j][3] = __expf(c[j][3] - mnB);
            sA += c[j][0] + c[j][1];
            sB += c[j][2] + c[j][3];
        }
        sA += __shfl_xor_sync(0xffffffffu, sA, 1);
        sA += __shfl_xor_sync(0xffffffffu, sA, 2);
        sB += __shfl_xor_sync(0xffffffffu, sB, 1);
        sB += __shfl_xor_sync(0xffffffffu, sB, 2);
        lA = lA * corrA + sA;
        lB = lB * corrB + sB;
#pragma unroll
        for (int j = 0; j < 8; j++) {
            o[j][0] *= corrA;
            o[j][1] *= corrA;
            o[j][2] *= corrB;
            o[j][3] *= corrB;
        }

        // ---- O += P @ V ----
#pragma unroll
        for (int t = 0; t < 4; t++) {
            uint32_t pah[4], pal[4];
#pragma unroll
            for (int e = 0; e < 4; e++) {
                int j = 2 * t + (e >> 1);
                float x = c[j][(e & 1) * 2];
                float y = c[j][(e & 1) * 2 + 1];
                __nv_bfloat16 hx = __float2bfloat16_rn(x);
                __nv_bfloat16 hy = __float2bfloat16_rn(y);
                pah[e] = pkbf2(hx, hy);
                pal[e] = pkbf2(__float2bfloat16_rn(x - __bfloat162float(hx)),
                               __float2bfloat16_rn(y - __bfloat162float(hy)));
            }
#pragma unroll
            for (int dch = 0; dch < 4; dch++) {
                uint32_t vbh[4], vbl[4];
                uint32_t off = sbase + 2 * KB_ +
                               (uint32_t)(((t * 16 + (lane & 15)) * AP + dch * 16) * 2) +
                               (lane >> 4) * 16;
                ldmx4t(vbh, off);
                ldmx4t(vbl, off + KB_);
                mma_bf16(o[dch * 2], pah, vbh[0], vbh[1]);
                mma_bf16(o[dch * 2], pah, vbl[0], vbl[1]);
                mma_bf16(o[dch * 2], pal, vbh[0], vbh[1]);
                mma_bf16(o[dch * 2 + 1], pah, vbh[2], vbh[3]);
                mma_bf16(o[dch * 2 + 1], pah, vbl[2], vbl[3]);
                mma_bf16(o[dch * 2 + 1], pal, vbh[2], vbh[3]);
            }
        }
        __syncthreads();  // stage reads done before it is overwritten next iter
    }

    // ---- epilogue: O /= l, split to bf16 hi/lo, scatter to [B,T,C] ----
    const float iA = 1.f / lA, iB = 1.f / lB;
    const int b = bh >> 4, h = bh & 15;
    const int rA = q0 + wid * 16 + (lane >> 2);
#pragma unroll
    for (int j = 0; j < 8; j++) {
        int d = h * HDc + j * 8 + (lane & 3) * 2;
        size_t iA0 = ((size_t)(b * Tc + rA)) * Cc + d;
        size_t iB0 = ((size_t)(b * Tc + rA + 8)) * Cc + d;
        float x0 = o[j][0] * iA, x1 = o[j][1] * iA;
        float x2 = o[j][2] * iB, x3 = o[j][3] * iB;
        __nv_bfloat16 h0 = __float2bfloat16_rn(x0), h1 = __float2bfloat16_rn(x1);
        __nv_bfloat16 h2 = __float2bfloat16_rn(x2), h3 = __float2bfloat16_rn(x3);
        *(uint32_t*)&g_athi[iA0] = pkbf2(h0, h1);
        *(uint32_t*)&g_atlo[iA0] =
            pkbf2(__float2bfloat16_rn(x0 - __bfloat162float(h0)),
                  __float2bfloat16_rn(x1 - __bfloat162float(h1)));
        *(uint32_t*)&g_athi[iB0] = pkbf2(h2, h3);
        *(uint32_t*)&g_atlo[iB0] =
            pkbf2(__float2bfloat16_rn(x2 - __bfloat162float(h2)),
                  __float2bfloat16_rn(x3 - __bfloat162float(h3)));
    }
}

// ---------------------------------------------------------------------------
// Launch
// ---------------------------------------------------------------------------
extern "C" void kernel_launch(void* const* d_in, const int* in_sizes, int n_in,
                              void* d_out, int out_size) {
    const float* x = (const float*)d_in[0];
    const float* w_attn = (const float*)d_in[1];
    const float* w_proj = (const float*)d_in[2];
    float* out = (float*)d_out;

    float* qkv_p = nullptr;
    cudaGetSymbolAddress((void**)&qkv_p, g_qkv);

    __nv_bfloat16 *xhi, *xlo, *wahi, *walo, *wphi, *wplo, *athi, *atlo;
    cudaGetSymbolAddress((void**)&xhi, g_xhi);
    cudaGetSymbolAddress((void**)&xlo, g_xlo);
    cudaGetSymbolAddress((void**)&wahi, g_wahi);
    cudaGetSymbolAddress((void**)&walo, g_walo);
    cudaGetSymbolAddress((void**)&wphi, g_wphi);
    cudaGetSymbolAddress((void**)&wplo, g_wplo);
    cudaGetSymbolAddress((void**)&athi, g_athi);
    cudaGetSymbolAddress((void**)&atlo, g_atlo);

    cudaFuncSetAttribute(gemm_mma, cudaFuncAttributeMaxDynamicSharedMemorySize,
                         GSMEM);
    cudaFuncSetAttribute(attn_mma, cudaFuncAttributeMaxDynamicSharedMemorySize,
                         ASMEM);

    compute_inv_kernel<<<1, 32>>>();

    {
        int n4 = (Mc * Cc) / 4;
        split_kernel<<<(n4 + 255) / 256, 256>>>(x, xhi, xlo, n4);
        n4 = (N3c * Cc) / 4;
        split_kernel<<<(n4 + 255) / 256, 256>>>(w_attn, wahi, walo, n4);
        n4 = (Cc * Cc) / 4;
        split_kernel<<<(n4 + 255) / 256, 256>>>(w_proj, wphi, wplo, n4);
    }

    {
        dim3 grid(N3c / 128, Mc / 128);
        gemm_mma<<<grid, 256, GSMEM>>>(xhi, xlo, wahi, walo, qkv_p, N3c, Cc);
    }

    norm_rope_kernel<<<Mc, 512>>>(qkv_p);

    {
        dim3 grid(Tc / 128, Bc * Hc);
        attn_mma<<<grid, 256, ASMEM>>>();
    }

    {
        dim3 grid(Cc / 128, Mc / 128);
        gemm_mma<<<grid, 256, GSMEM>>>(athi, atlo, wphi, wplo, out, Cc, Cc);
    }
}